// round 7
// baseline (speedup 1.0000x reference)
#include <cuda_runtime.h>
#include <cuda_bf16.h>
#include <math.h>

// ---------------------------------------------------------------------------
// Problem constants
// ---------------------------------------------------------------------------
#define BB    128
#define TT    384
#define HH    1024
#define N3    3072
#define KK    1024
#define MFULL (BB*TT)

#define NBLK  128           // persistent recurrence blocks (1/SM)
#define UPB   8             // hidden units per recurrence block
#define HCH   16            // h staging chunk width (k)

// ---------------------------------------------------------------------------
// Scratch (device globals -- allocation-free per harness rules)
// ---------------------------------------------------------------------------
__device__ float g_xg [(size_t)MFULL * N3];
__device__ float g_yA [(size_t)MFULL * HH];
__device__ float g_yB [(size_t)MFULL * HH];
__device__ float g_h0 [BB * HH];
__device__ float g_h1 [BB * HH];

// grid barrier state (identical semantics to the validated R3 barrier)
__device__ volatile unsigned g_barA = 0;
__device__ volatile unsigned g_gen  = 0;

__device__ __forceinline__ void grid_sync(unsigned nb)
{
    __syncthreads();
    if (threadIdx.x == 0) {
        unsigned old = g_gen;
        __threadfence();
        if (atomicAdd((unsigned*)&g_barA, 1u) == nb - 1u) {
            g_barA = 0;
            __threadfence();
            atomicAdd((unsigned*)&g_gen, 1u);
        } else {
            while (g_gen == old) { }
        }
        __threadfence();
    }
    __syncthreads();
}

// ---------------------------------------------------------------------------
// TF32 helpers: hi/lo split and m16n8k8 mma
// ---------------------------------------------------------------------------
__device__ __forceinline__ float2 split_tf32(float x)
{
    unsigned hi; asm("cvt.rna.tf32.f32 %0, %1;" : "=r"(hi) : "f"(x));
    float hif = __uint_as_float(hi);
    unsigned lo; asm("cvt.rna.tf32.f32 %0, %1;" : "=r"(lo) : "f"(x - hif));
    return make_float2(hif, __uint_as_float(lo));
}

__device__ __forceinline__ void mma_tf32(float* d, float a0, float a1, float a2,
                                         float a3, float b0, float b1)
{
    asm volatile(
        "mma.sync.aligned.m16n8k8.row.col.f32.tf32.tf32.f32 "
        "{%0,%1,%2,%3}, {%4,%5,%6,%7}, {%8,%9}, {%0,%1,%2,%3};"
        : "+f"(d[0]), "+f"(d[1]), "+f"(d[2]), "+f"(d[3])
        : "r"(__float_as_uint(a0)), "r"(__float_as_uint(a1)),
          "r"(__float_as_uint(a2)), "r"(__float_as_uint(a3)),
          "r"(__float_as_uint(b0)), "r"(__float_as_uint(b1)));
}

// 3xTF32: d += Ahi*Blo + Alo*Bhi + Ahi*Bhi   (A*, B* carry {hi,lo} in {x,y})
__device__ __forceinline__ void mma3(float* d, float2 A0, float2 A1, float2 A2,
                                     float2 A3, float2 B0, float2 B1)
{
    mma_tf32(d, A0.x, A1.x, A2.x, A3.x, B0.y, B1.y);
    mma_tf32(d, A0.y, A1.y, A2.y, A3.y, B0.x, B1.x);
    mma_tf32(d, A0.x, A1.x, A2.x, A3.x, B0.x, B1.x);
}

// ---------------------------------------------------------------------------
// xg GEMM: C[m,n] = bias[n] + A[m,:].W[n,:]   (TN, tf32 3x)
// Block tile 128x64, 8 warps (4m x 2n grid), warp tile 32x32, K chunks of 32.
// smem tiles hold (hi,lo) float2 with XOR swizzle: k' = k ^ ((row&3)<<2).
// ---------------------------------------------------------------------------
#define XG_SMEM ((128*32 + 64*32) * (int)sizeof(float2))   // 49152 B

__global__ __launch_bounds__(256) void gemm_xg(
    const float* __restrict__ A, const float* __restrict__ W,
    const float* __restrict__ bias, float* __restrict__ C)
{
    extern __shared__ float2 sm[];
    float2* sA = sm;               // [128][32] swizzled
    float2* sB = sm + 128 * 32;    // [64][32]  swizzled

    const int tid  = threadIdx.x;
    const int lane = tid & 31;
    const int w    = tid >> 5;
    const int wm   = w & 3, wn = w >> 2;
    const int qr   = lane >> 2;          // 0..7
    const int lq   = lane & 3;           // 0..3
    const int m0   = blockIdx.y * 128;
    const int n0   = blockIdx.x * 64;

    float D[2][4][4] = {};

    for (int kc = 0; kc < KK; kc += 32) {
        // stage A tile 128x32 (split fp32 -> hi/lo)
        {
            int r  = tid >> 1;
            int kq = (tid & 1) << 4;
            const float* src = A + (size_t)(m0 + r) * KK + kc + kq;
            float2* drow = &sA[r * 32];
            int swz = (r & 3) << 2;
            #pragma unroll
            for (int g = 0; g < 16; g += 4) {
                float4 v = *(const float4*)(src + g);
                int ks = (kq + g) ^ swz;
                drow[ks + 0] = split_tf32(v.x);
                drow[ks + 1] = split_tf32(v.y);
                drow[ks + 2] = split_tf32(v.z);
                drow[ks + 3] = split_tf32(v.w);
            }
        }
        // stage B tile 64x32
        {
            int r  = tid >> 2;
            int kq = (tid & 3) << 3;
            const float* src = W + (size_t)(n0 + r) * KK + kc + kq;
            float2* drow = &sB[r * 32];
            int swz = (r & 3) << 2;
            #pragma unroll
            for (int g = 0; g < 8; g += 4) {
                float4 v = *(const float4*)(src + g);
                int ks = (kq + g) ^ swz;
                drow[ks + 0] = split_tf32(v.x);
                drow[ks + 1] = split_tf32(v.y);
                drow[ks + 2] = split_tf32(v.z);
                drow[ks + 3] = split_tf32(v.w);
            }
        }
        __syncthreads();

        #pragma unroll
        for (int kt = 0; kt < 32; kt += 8) {
            float2 Bf[4][2];
            #pragma unroll
            for (int fn = 0; fn < 4; ++fn) {
                int nb  = wn * 32 + fn * 8 + qr;
                int swz = (nb & 3) << 2;
                Bf[fn][0] = sB[nb * 32 + ((kt + lq) ^ swz)];
                Bf[fn][1] = sB[nb * 32 + ((kt + 4 + lq) ^ swz)];
            }
            #pragma unroll
            for (int f = 0; f < 2; ++f) {
                int ra  = wm * 32 + f * 16 + qr;
                int swz = (ra & 3) << 2;
                int k0  = (kt + lq) ^ swz;
                int k1  = (kt + 4 + lq) ^ swz;
                float2 A0 = sA[ra * 32 + k0];
                float2 A1 = sA[(ra + 8) * 32 + k0];   // (ra+8)&3 == ra&3
                float2 A2 = sA[ra * 32 + k1];
                float2 A3 = sA[(ra + 8) * 32 + k1];
                #pragma unroll
                for (int fn = 0; fn < 4; ++fn)
                    mma3(D[f][fn], A0, A1, A2, A3, Bf[fn][0], Bf[fn][1]);
            }
        }
        __syncthreads();
    }

    #pragma unroll
    for (int f = 0; f < 2; ++f)
        #pragma unroll
        for (int i = 0; i < 2; ++i) {
            int m = m0 + wm * 32 + f * 16 + qr + 8 * i;
            #pragma unroll
            for (int fn = 0; fn < 4; ++fn) {
                int n = n0 + wn * 32 + fn * 8 + (lq << 1);
                float2 bv = *(const float2*)&bias[n];
                float2 o = make_float2(D[f][fn][2*i] + bv.x, D[f][fn][2*i+1] + bv.y);
                *(float2*)&C[(size_t)m * N3 + n] = o;
            }
        }
}

// ---------------------------------------------------------------------------
// Persistent GRU recurrence (tensor-core h-GEMM, tf32 3x).
// 128 blocks x 256 threads (8 warps), 1 block/SM. Block owns units
// j0..j0+7; its 24 Whh rows live in smem pre-split (hi,lo) for the whole
// pass (196 KB). Per step: stage h in 16-k chunks (16 KB), warp w computes
// batches 16w..16w+15 x 3 gate n-tiles; gates evaluated in D registers.
// REC_SMEM = 212,992 B (19 KB under the 227 KB opt-in ceiling).
// ---------------------------------------------------------------------------
#define SW_F2 (24 * 1024)                 // W slice float2 count
#define SH_F2 (128 * HCH)                 // h chunk float2 count (2048)
#define REC_SMEM ((SW_F2 + SH_F2) * (int)sizeof(float2))   // 212992 B

__device__ __forceinline__ float sigf(float x) { return 1.0f / (1.0f + expf(-x)); }

__global__ __launch_bounds__(256) void gru_recurrence(
    const float* __restrict__ xg, const float* __restrict__ Whh,
    const float* __restrict__ bhh, float* __restrict__ hbuf0,
    float* __restrict__ hbuf1, float* __restrict__ y)
{
    extern __shared__ float2 sm[];
    float2* sW = sm;            // [24][1024] swizzled (hi,lo)
    float2* sH = sm + SW_F2;    // [128][16]  swizzled (hi,lo)

    const int tid  = threadIdx.x;
    const int lane = tid & 31;
    const int w    = tid >> 5;
    const int qr   = lane >> 2;          // 0..7 (B n-index / A row-in-quad)
    const int lq   = lane & 3;
    const int qcol = lq << 1;
    const int j0   = blockIdx.x * UPB;

    // one-time: split this block's 24 Whh rows into smem
    for (int idx = tid; idx < 24 * 256; idx += 256) {
        int r  = idx >> 8;                // 0..23 = g*8+u
        int k4 = (idx & 255) << 2;
        int g  = r >> 3, u = r & 7;
        float4 v = *(const float4*)&Whh[(size_t)(g * HH + j0 + u) * KK + k4];
        int ks = k4 ^ ((u & 3) << 2);
        float2* dst = &sW[r * 1024 + ks];
        dst[0] = split_tf32(v.x); dst[1] = split_tf32(v.y);
        dst[2] = split_tf32(v.z); dst[3] = split_tf32(v.w);
    }
    // per-thread gate biases for owned (j) pair
    const float brj0 = bhh[j0 + qcol],          brj1 = bhh[j0 + qcol + 1];
    const float bzj0 = bhh[HH + j0 + qcol],     bzj1 = bhh[HH + j0 + qcol + 1];
    const float bnj0 = bhh[2*HH + j0 + qcol],   bnj1 = bhh[2*HH + j0 + qcol + 1];
    __syncthreads();

    const float* hin  = hbuf0;
    float*       hout = hbuf1;

    for (int t = 0; t < TT; ++t) {
        float Dr[4] = {}, Dz[4] = {}, Dn[4] = {};

        for (int kc = 0; kc < KK; kc += HCH) {
            // stage h chunk 128x16 (split fp32 -> hi/lo)
            {
                int r  = tid >> 1;
                int kq = (tid & 1) << 3;
                const float* src = hin + (size_t)r * KK + kc + kq;
                float2* drow = &sH[r * HCH];
                int swz = (r & 3) << 2;
                #pragma unroll
                for (int g = 0; g < 8; g += 4) {
                    float4 v = *(const float4*)(src + g);
                    int ks = (kq + g) ^ swz;
                    drow[ks + 0] = split_tf32(v.x);
                    drow[ks + 1] = split_tf32(v.y);
                    drow[ks + 2] = split_tf32(v.z);
                    drow[ks + 3] = split_tf32(v.w);
                }
            }
            __syncthreads();

            #pragma unroll
            for (int kt = 0; kt < HCH; kt += 8) {
                int ra  = 16 * w + qr;
                int swzA = (ra & 3) << 2;
                int ka0 = (kt + lq) ^ swzA;
                int ka1 = (kt + 4 + lq) ^ swzA;
                float2 A0 = sH[ra * HCH + ka0];
                float2 A1 = sH[(ra + 8) * HCH + ka0];
                float2 A2 = sH[ra * HCH + ka1];
                float2 A3 = sH[(ra + 8) * HCH + ka1];

                int swzB = (qr & 3) << 2;
                int kb0 = (kc + kt + lq) ^ swzB;
                int kb1 = (kc + kt + 4 + lq) ^ swzB;
                float2 B0r = sW[(0 * 8 + qr) * 1024 + kb0];
                float2 B1r = sW[(0 * 8 + qr) * 1024 + kb1];
                float2 B0z = sW[(1 * 8 + qr) * 1024 + kb0];
                float2 B1z = sW[(1 * 8 + qr) * 1024 + kb1];
                float2 B0n = sW[(2 * 8 + qr) * 1024 + kb0];
                float2 B1n = sW[(2 * 8 + qr) * 1024 + kb1];

                mma3(Dr, A0, A1, A2, A3, B0r, B1r);
                mma3(Dz, A0, A1, A2, A3, B0z, B1z);
                mma3(Dn, A0, A1, A2, A3, B0n, B1n);
            }
            __syncthreads();
        }

        // fused gates: thread owns batches {16w+qr, 16w+qr+8} x units {j0+qcol, +1}
        #pragma unroll
        for (int i = 0; i < 2; ++i) {
            const int b = 16 * w + qr + 8 * i;
            const size_t xo = ((size_t)b * TT + t) * N3 + j0 + qcol;
            float2 xr = *(const float2*)&xg[xo];
            float2 xz = *(const float2*)&xg[xo + HH];
            float2 xn = *(const float2*)&xg[xo + 2 * HH];
            float2 hp = *(const float2*)&hin[(size_t)b * HH + j0 + qcol];

            float r0 = sigf(xr.x + Dr[2*i]   + brj0);
            float r1 = sigf(xr.y + Dr[2*i+1] + brj1);
            float z0 = sigf(xz.x + Dz[2*i]   + bzj0);
            float z1 = sigf(xz.y + Dz[2*i+1] + bzj1);
            float n0 = tanhf(xn.x + r0 * (Dn[2*i]   + bnj0));
            float n1 = tanhf(xn.y + r1 * (Dn[2*i+1] + bnj1));
            float2 hv = make_float2((1.0f - z0) * n0 + z0 * hp.x,
                                    (1.0f - z1) * n1 + z1 * hp.y);
            *(float2*)&hout[(size_t)b * HH + j0 + qcol] = hv;
            if (y) *(float2*)&y[((size_t)b * TT + t) * HH + j0 + qcol] = hv;
        }

        grid_sync(NBLK);
        const float* tmp = hin; hin = hout; hout = (float*)tmp;
    }
    // TT even -> final hidden ends in hbuf0
}

// ---------------------------------------------------------------------------
// predictions[b] = dot(h[b,:], lin_W) + lin_b
// ---------------------------------------------------------------------------
__global__ __launch_bounds__(256) void final_pred(
    const float* __restrict__ h, const float* __restrict__ W,
    const float* __restrict__ bias, float* __restrict__ out)
{
    int b = blockIdx.x;
    float s = 0.f;
    for (int j = threadIdx.x; j < HH; j += 256)
        s += h[(size_t)b * HH + j] * W[j];
    #pragma unroll
    for (int o = 16; o; o >>= 1) s += __shfl_xor_sync(0xFFFFFFFFu, s, o);
    __shared__ float ws[8];
    if ((threadIdx.x & 31) == 0) ws[threadIdx.x >> 5] = s;
    __syncthreads();
    if (threadIdx.x == 0) {
        float t = 0.f;
        #pragma unroll
        for (int k = 0; k < 8; ++k) t += ws[k];
        out[b] = t + bias[0];
    }
}

// ---------------------------------------------------------------------------
// Launch — 13 graph nodes
// ---------------------------------------------------------------------------
extern "C" void kernel_launch(void* const* d_in, const int* in_sizes, int n_in,
                              void* d_out, int out_size)
{
    const float* rand_input = (const float*)d_in[1];
    const float* h0   = (const float*)d_in[2];
    const float* Wih0 = (const float*)d_in[7];
    const float* Whh0 = (const float*)d_in[8];
    const float* bih0 = (const float*)d_in[9];
    const float* bhh0 = (const float*)d_in[10];
    const float* Wih1 = (const float*)d_in[11];
    const float* Whh1 = (const float*)d_in[12];
    const float* bih1 = (const float*)d_in[13];
    const float* bhh1 = (const float*)d_in[14];
    const float* linW = (const float*)d_in[15];
    const float* linb = (const float*)d_in[16];
    float* out = (float*)d_out;

    float *xg, *yA, *yB, *h0b, *h1b;
    cudaGetSymbolAddress((void**)&xg,  g_xg);
    cudaGetSymbolAddress((void**)&yA,  g_yA);
    cudaGetSymbolAddress((void**)&yB,  g_yB);
    cudaGetSymbolAddress((void**)&h0b, g_h0);
    cudaGetSymbolAddress((void**)&h1b, g_h1);

    cudaFuncSetAttribute(gru_recurrence,
                         cudaFuncAttributeMaxDynamicSharedMemorySize, REC_SMEM);
    cudaFuncSetAttribute(gemm_xg,
                         cudaFuncAttributeMaxDynamicSharedMemorySize, XG_SMEM);

    dim3 blk(256);
    dim3 grid_xg(N3 / 64, MFULL / 128);   // 48 x 384

    auto run_pass = [&](const float* x, const float* Wih, const float* bih,
                        const float* Whh, const float* bhh, float* y) {
        gemm_xg<<<grid_xg, blk, XG_SMEM>>>(x, Wih, bih, xg);
        gru_recurrence<<<NBLK, blk, REC_SMEM>>>(xg, Whh, bhh, h0b, h1b, y);
    };

    const size_t HBYTES = (size_t)BB * HH * sizeof(float);

    cudaMemcpyAsync(h0b, h0, HBYTES, cudaMemcpyDeviceToDevice);
    run_pass(rand_input, Wih0, bih0, Whh0, bhh0, yA);

    cudaMemcpyAsync(h0b, h0 + (size_t)BB * HH, HBYTES, cudaMemcpyDeviceToDevice);
    run_pass(yA, Wih1, bih1, Whh1, bhh1, yB);

    cudaMemsetAsync(h0b, 0, HBYTES);
    run_pass(yB, Wih0, bih0, Whh0, bhh0, yA);

    cudaMemsetAsync(h0b, 0, HBYTES);
    run_pass(yA, Wih1, bih1, Whh1, bhh1, nullptr);

    final_pred<<<BB, blk>>>(h0b, linW, linb, out);
}

// round 9
// speedup vs baseline: 2.9420x; 2.9420x over previous
#include <cuda_runtime.h>
#include <cuda_fp16.h>
#include <math.h>

// ---------------------------------------------------------------------------
// Problem constants
// ---------------------------------------------------------------------------
#define BB    128
#define TT    384
#define HH    1024
#define N3    3072
#define KK    1024
#define KP    (KK/2)        // 512 fp16-pairs per row
#define MFULL (BB*TT)

#define NBLK  128           // persistent recurrence blocks (1/SM)
#define UPB   8             // hidden units per recurrence block
#define HCH   64            // h staging chunk (k elems) -> 32 pairs
#define NCH   (KK/HCH)      // 16 chunks per step

// ---------------------------------------------------------------------------
// Scratch (device globals -- allocation-free per harness rules)
// ---------------------------------------------------------------------------
__device__ float g_xg [(size_t)MFULL * N3];        // 604 MB fp32 input projections
__device__ uint2 g_inS [(size_t)MFULL * KP];       // 201 MB split rand_input
__device__ uint2 g_yAS [(size_t)MFULL * KP];       // 201 MB split layer out ping
__device__ uint2 g_yBS [(size_t)MFULL * KP];       // 201 MB split layer out pong
__device__ uint2 g_WihS[2][(size_t)N3 * KP];       // 2x12.6 MB split Wih
__device__ uint2 g_WhhS[2][(size_t)N3 * KP];       // 2x12.6 MB split Whh
__device__ uint2 g_hS0 [BB * KP];                  // split hidden ping
__device__ uint2 g_hS1 [BB * KP];                  // split hidden pong

// grid barrier (validated R3/R7 semantics)
__device__ volatile unsigned g_barA = 0;
__device__ volatile unsigned g_gen  = 0;

__device__ __forceinline__ void grid_sync(unsigned nb)
{
    __syncthreads();
    if (threadIdx.x == 0) {
        unsigned old = g_gen;
        __threadfence();
        if (atomicAdd((unsigned*)&g_barA, 1u) == nb - 1u) {
            g_barA = 0;
            __threadfence();
            atomicAdd((unsigned*)&g_gen, 1u);
        } else {
            while (g_gen == old) { }
        }
        __threadfence();
    }
    __syncthreads();
}

// ---------------------------------------------------------------------------
// Helpers: fp16 hi/lo split pairs, cp.async, m16n8k16 mma
// ---------------------------------------------------------------------------
__device__ __forceinline__ uint2 splitpair(float x0, float x1)
{
    __half h0 = __float2half_rn(x0), h1 = __float2half_rn(x1);
    float  r0 = x0 - __half2float(h0), r1 = x1 - __half2float(h1);
    __half l0 = __float2half_rn(r0), l1 = __float2half_rn(r1);
    uint2 u;
    u.x = (unsigned)__half_as_ushort(h0) | ((unsigned)__half_as_ushort(h1) << 16);
    u.y = (unsigned)__half_as_ushort(l0) | ((unsigned)__half_as_ushort(l1) << 16);
    return u;
}
__device__ __forceinline__ float lo_f(unsigned u) { return __half2float(__ushort_as_half((unsigned short)(u & 0xFFFF))); }
__device__ __forceinline__ float hi_f(unsigned u) { return __half2float(__ushort_as_half((unsigned short)(u >> 16))); }

__device__ __forceinline__ unsigned sptr(const void* p)
{ return (unsigned)__cvta_generic_to_shared(p); }
__device__ __forceinline__ void cpa16(unsigned d, const void* s)
{ asm volatile("cp.async.cg.shared.global [%0], [%1], 16;" :: "r"(d), "l"(s)); }
#define CP_COMMIT() asm volatile("cp.async.commit_group;")
#define CP_WAIT1()  asm volatile("cp.async.wait_group 1;")
#define CP_WAIT0()  asm volatile("cp.async.wait_group 0;")

__device__ __forceinline__ void mma_f16(float* d, unsigned a0, unsigned a1,
                                        unsigned a2, unsigned a3,
                                        unsigned b0, unsigned b1)
{
    asm volatile(
        "mma.sync.aligned.m16n8k16.row.col.f32.f16.f16.f32 "
        "{%0,%1,%2,%3}, {%4,%5,%6,%7}, {%8,%9}, {%0,%1,%2,%3};"
        : "+f"(d[0]), "+f"(d[1]), "+f"(d[2]), "+f"(d[3])
        : "r"(a0), "r"(a1), "r"(a2), "r"(a3), "r"(b0), "r"(b1));
}
// 3xFP16: d += Ahi*Blo + Alo*Bhi + Ahi*Bhi   (uint2 .x=hi-pair, .y=lo-pair)
__device__ __forceinline__ void mma3h(float* d, uint2 A0, uint2 A1, uint2 A2,
                                      uint2 A3, uint2 B0, uint2 B1)
{
    mma_f16(d, A0.x, A1.x, A2.x, A3.x, B0.y, B1.y);
    mma_f16(d, A0.y, A1.y, A2.y, A3.y, B0.x, B1.x);
    mma_f16(d, A0.x, A1.x, A2.x, A3.x, B0.x, B1.x);
}

// ---------------------------------------------------------------------------
// Prep: fp32 -> packed (hi,lo) fp16 pair split
// ---------------------------------------------------------------------------
__global__ __launch_bounds__(256) void split_pairs(
    const float2* __restrict__ src, uint2* __restrict__ dst, int n)
{
    int i = blockIdx.x * blockDim.x + threadIdx.x;
    if (i < n) { float2 v = src[i]; dst[i] = splitpair(v.x, v.y); }
}

// ---------------------------------------------------------------------------
// xg GEMM (fp16-3x): C[m,n] = bias[n] + A[m,:].W[n,:]
// A, W pre-split packed pairs. Block tile 128x64, 8 warps (4m x 2n),
// warp tile 32x32, K chunk = 32 elems (16 pairs), cp.async double-buffered.
// smem pair swizzle: ks = pair ^ ((row&3)<<2)  (granule-preserving for 16B).
// ---------------------------------------------------------------------------
#define XG_SMEM ((2*(128*16) + 2*(64*16)) * (int)sizeof(uint2))   // 49152 B

__global__ __launch_bounds__(256) void gemm_xg(
    const uint2* __restrict__ A, const uint2* __restrict__ W,
    const float* __restrict__ bias, float* __restrict__ C)
{
    extern __shared__ uint2 smv[];
    uint2* sA[2] = { smv,            smv + 128*16 };
    uint2* sB[2] = { smv + 2*128*16, smv + 2*128*16 + 64*16 };

    const int tid  = threadIdx.x;
    const int lane = tid & 31;
    const int w    = tid >> 5;
    const int wm   = w & 3, wn = w >> 2;
    const int qr   = lane >> 2;
    const int lq   = lane & 3;
    const int m0   = blockIdx.y * 128;
    const int n0   = blockIdx.x * 64;

    float D[2][4][4] = {};

    auto stage = [&](int kc, int s) {
        #pragma unroll
        for (int u = 0; u < 4; ++u) {              // A: 1024 granules
            int gi = tid + u * 256;
            int row = gi >> 3, g = gi & 7;
            const uint2* src = A + (size_t)(m0 + row) * KP + kc * 16 + g * 2;
            int ks = (g * 2) ^ ((row & 3) << 2);
            cpa16(sptr(sA[s] + row * 16 + ks), src);
        }
        #pragma unroll
        for (int u = 0; u < 2; ++u) {              // B: 512 granules
            int gi = tid + u * 256;
            int row = gi >> 3, g = gi & 7;
            const uint2* src = W + (size_t)(n0 + row) * KP + kc * 16 + g * 2;
            int ks = (g * 2) ^ ((row & 3) << 2);
            cpa16(sptr(sB[s] + row * 16 + ks), src);
        }
        CP_COMMIT();
    };

    stage(0, 0);
    for (int kc = 0; kc < 32; ++kc) {
        if (kc < 31) { stage(kc + 1, (kc + 1) & 1); CP_WAIT1(); }
        else         { CP_WAIT0(); }
        __syncthreads();
        const uint2* bA = sA[kc & 1];
        const uint2* bB = sB[kc & 1];

        #pragma unroll
        for (int kt = 0; kt < 2; ++kt) {
            int pb = kt * 8;
            uint2 Bf[4][2];
            #pragma unroll
            for (int fn = 0; fn < 4; ++fn) {
                int nb = wn * 32 + fn * 8 + qr;
                int swz = (nb & 3) << 2;
                Bf[fn][0] = bB[nb * 16 + ((pb + lq) ^ swz)];
                Bf[fn][1] = bB[nb * 16 + ((pb + 4 + lq) ^ swz)];
            }
            #pragma unroll
            for (int f = 0; f < 2; ++f) {
                int ra = wm * 32 + f * 16 + qr;
                int swz = (ra & 3) << 2;
                int k0 = (pb + lq) ^ swz, k1 = (pb + 4 + lq) ^ swz;
                uint2 A0 = bA[ra * 16 + k0];
                uint2 A1 = bA[(ra + 8) * 16 + k0];
                uint2 A2 = bA[ra * 16 + k1];
                uint2 A3 = bA[(ra + 8) * 16 + k1];
                #pragma unroll
                for (int fn = 0; fn < 4; ++fn)
                    mma3h(D[f][fn], A0, A1, A2, A3, Bf[fn][0], Bf[fn][1]);
            }
        }
        __syncthreads();
    }

    #pragma unroll
    for (int f = 0; f < 2; ++f)
        #pragma unroll
        for (int i = 0; i < 2; ++i) {
            int m = m0 + wm * 32 + f * 16 + qr + 8 * i;
            #pragma unroll
            for (int fn = 0; fn < 4; ++fn) {
                int n = n0 + wn * 32 + fn * 8 + (lq << 1);
                float2 bv = *(const float2*)&bias[n];
                float2 o = make_float2(D[f][fn][2*i] + bv.x, D[f][fn][2*i+1] + bv.y);
                *(float2*)&C[(size_t)m * N3 + n] = o;
            }
        }
}

// ---------------------------------------------------------------------------
// Persistent GRU recurrence (fp16-3x mma, split-form state).
// 128 blocks x 256 threads (8 warps), 1 block/SM. Block owns units
// j0..j0+7: 24 pre-split Whh rows in smem for the whole pass (96 KB).
// Per step: cp.async double-buffered h chunks (pure copy, no conversion),
// 9 mma per kt16 per warp, gates in D regs, h written back pre-split.
// ---------------------------------------------------------------------------
#define SW_U2  (24 * KP)                 // 12288 uint2 = 98304 B
#define SHC_U2 (128 * 32)                // per h chunk: 4096 uint2 = 32768 B
#define REC_SMEM ((SW_U2 + 2 * SHC_U2) * (int)sizeof(uint2))   // 163840 B

__device__ __forceinline__ float sigf(float x) { return 1.0f / (1.0f + expf(-x)); }

__global__ __launch_bounds__(256) void gru_recurrence(
    const float* __restrict__ xg, const uint2* __restrict__ WhhS,
    const float* __restrict__ bhh, uint2* __restrict__ hS0,
    uint2* __restrict__ hS1, uint2* __restrict__ yS)
{
    extern __shared__ uint2 smv[];
    uint2* sW    = smv;                         // [24][512] swizzled
    uint2* sH[2] = { smv + SW_U2, smv + SW_U2 + SHC_U2 };   // [128][32]

    const int tid  = threadIdx.x;
    const int lane = tid & 31;
    const int w    = tid >> 5;
    const int qr   = lane >> 2;
    const int lq   = lane & 3;
    const int j0   = blockIdx.x * UPB;

    // one-time: copy this block's 24 pre-split Whh rows into smem (swizzled)
    for (int idx = tid; idx < 24 * 256; idx += 256) {
        int r = idx >> 8;                 // 0..23 = gate*8+u
        int g = idx & 255;                // granule (2 pairs)
        int gate = r >> 3, u = r & 7;
        const uint2* src = WhhS + (size_t)(gate * HH + j0 + u) * KP + g * 2;
        uint4 v = *(const uint4*)src;
        int ks = (g * 2) ^ ((r & 3) << 2);
        sW[r * KP + ks]     = make_uint2(v.x, v.y);
        sW[r * KP + ks + 1] = make_uint2(v.z, v.w);
    }
    const int qcol = lq << 1;
    const float brj0 = bhh[j0 + qcol],        brj1 = bhh[j0 + qcol + 1];
    const float bzj0 = bhh[HH + j0 + qcol],   bzj1 = bhh[HH + j0 + qcol + 1];
    const float bnj0 = bhh[2*HH + j0 + qcol], bnj1 = bhh[2*HH + j0 + qcol + 1];
    __syncthreads();

    const uint2* hin  = hS0;
    uint2*       hout = hS1;

    for (int t = 0; t < TT; ++t) {
        float Dr[4] = {}, Dz[4] = {}, Dn[4] = {};

        auto stageH = [&](int c, int s) {
            #pragma unroll
            for (int u = 0; u < 8; ++u) {          // 2048 granules
                int gi = tid + u * 256;
                int row = gi >> 4, g = gi & 15;
                const uint2* src = hin + (size_t)row * KP + c * 32 + g * 2;
                int ks = (g * 2) ^ ((row & 3) << 2);
                cpa16(sptr(sH[s] + row * 32 + ks), src);
            }
            CP_COMMIT();
        };

        stageH(0, 0);
        for (int c = 0; c < NCH; ++c) {
            if (c < NCH - 1) { stageH(c + 1, (c + 1) & 1); CP_WAIT1(); }
            else             { CP_WAIT0(); }
            __syncthreads();
            const uint2* bH = sH[c & 1];

            #pragma unroll
            for (int kt = 0; kt < 4; ++kt) {
                int pb = kt * 8;
                int ra = 16 * w + qr;
                int swzA = (ra & 3) << 2;
                int k0 = (pb + lq) ^ swzA, k1 = (pb + 4 + lq) ^ swzA;
                uint2 A0 = bH[ra * 32 + k0];
                uint2 A1 = bH[(ra + 8) * 32 + k0];
                uint2 A2 = bH[ra * 32 + k1];
                uint2 A3 = bH[(ra + 8) * 32 + k1];

                int pW = c * 32 + pb;
                {
                    int r = 0 * 8 + qr, swz = (r & 3) << 2;
                    mma3h(Dr, A0, A1, A2, A3,
                          sW[r * KP + ((pW + lq) ^ swz)],
                          sW[r * KP + ((pW + 4 + lq) ^ swz)]);
                }
                {
                    int r = 1 * 8 + qr, swz = (r & 3) << 2;
                    mma3h(Dz, A0, A1, A2, A3,
                          sW[r * KP + ((pW + lq) ^ swz)],
                          sW[r * KP + ((pW + 4 + lq) ^ swz)]);
                }
                {
                    int r = 2 * 8 + qr, swz = (r & 3) << 2;
                    mma3h(Dn, A0, A1, A2, A3,
                          sW[r * KP + ((pW + lq) ^ swz)],
                          sW[r * KP + ((pW + 4 + lq) ^ swz)]);
                }
            }
            __syncthreads();
        }

        // gates: thread owns batches {16w+qr, +8} x unit pair (j0+2lq, j0+2lq+1)
        const int pidx = (j0 >> 1) + lq;
        #pragma unroll
        for (int i = 0; i < 2; ++i) {
            const int b = 16 * w + qr + 8 * i;
            const size_t xo = ((size_t)b * TT + t) * N3 + j0 + qcol;
            float2 xr = *(const float2*)&xg[xo];
            float2 xz = *(const float2*)&xg[xo + HH];
            float2 xn = *(const float2*)&xg[xo + 2 * HH];
            uint2  hs = hin[(size_t)b * KP + pidx];
            float hp0 = lo_f(hs.x) + lo_f(hs.y);
            float hp1 = hi_f(hs.x) + hi_f(hs.y);

            float r0 = sigf(xr.x + Dr[2*i]   + brj0);
            float r1 = sigf(xr.y + Dr[2*i+1] + brj1);
            float z0 = sigf(xz.x + Dz[2*i]   + bzj0);
            float z1 = sigf(xz.y + Dz[2*i+1] + bzj1);
            float n0 = tanhf(xn.x + r0 * (Dn[2*i]   + bnj0));
            float n1 = tanhf(xn.y + r1 * (Dn[2*i+1] + bnj1));
            float h0 = (1.0f - z0) * n0 + z0 * hp0;
            float h1 = (1.0f - z1) * n1 + z1 * hp1;
            uint2 pk = splitpair(h0, h1);
            hout[(size_t)b * KP + pidx] = pk;
            if (yS) yS[((size_t)b * TT + t) * KP + pidx] = pk;
        }

        grid_sync(NBLK);
        const uint2* tmp = hin; hin = hout; hout = (uint2*)tmp;
    }
    // TT even -> final hidden ends in hS0
}

// ---------------------------------------------------------------------------
// predictions[b] = dot(h[b,:], lin_W) + lin_b   (h reconstructed hi+lo)
// ---------------------------------------------------------------------------
__global__ __launch_bounds__(256) void final_pred(
    const uint2* __restrict__ hS, const float* __restrict__ W,
    const float* __restrict__ bias, float* __restrict__ out)
{
    int b = blockIdx.x;
    float s = 0.f;
    for (int p = threadIdx.x; p < KP; p += 256) {
        uint2 u = hS[(size_t)b * KP + p];
        s += (lo_f(u.x) + lo_f(u.y)) * W[2 * p]
           + (hi_f(u.x) + hi_f(u.y)) * W[2 * p + 1];
    }
    #pragma unroll
    for (int o = 16; o; o >>= 1) s += __shfl_xor_sync(0xFFFFFFFFu, s, o);
    __shared__ float ws[8];
    if ((threadIdx.x & 31) == 0) ws[threadIdx.x >> 5] = s;
    __syncthreads();
    if (threadIdx.x == 0) {
        float t = 0.f;
        #pragma unroll
        for (int k = 0; k < 8; ++k) t += ws[k];
        out[b] = t + bias[0];
    }
}

// ---------------------------------------------------------------------------
// Launch — ~20 graph nodes
// ---------------------------------------------------------------------------
extern "C" void kernel_launch(void* const* d_in, const int* in_sizes, int n_in,
                              void* d_out, int out_size)
{
    const float* rand_input = (const float*)d_in[1];
    const float* h0   = (const float*)d_in[2];
    const float* Wih0 = (const float*)d_in[7];
    const float* Whh0 = (const float*)d_in[8];
    const float* bih0 = (const float*)d_in[9];
    const float* bhh0 = (const float*)d_in[10];
    const float* Wih1 = (const float*)d_in[11];
    const float* Whh1 = (const float*)d_in[12];
    const float* bih1 = (const float*)d_in[13];
    const float* bhh1 = (const float*)d_in[14];
    const float* linW = (const float*)d_in[15];
    const float* linb = (const float*)d_in[16];
    float* out = (float*)d_out;

    float *xg;
    uint2 *inS, *yAS, *yBS, *WihS, *WhhS, *hS0, *hS1;
    cudaGetSymbolAddress((void**)&xg,   g_xg);
    cudaGetSymbolAddress((void**)&inS,  g_inS);
    cudaGetSymbolAddress((void**)&yAS,  g_yAS);
    cudaGetSymbolAddress((void**)&yBS,  g_yBS);
    cudaGetSymbolAddress((void**)&WihS, g_WihS);
    cudaGetSymbolAddress((void**)&WhhS, g_WhhS);
    cudaGetSymbolAddress((void**)&hS0,  g_hS0);
    cudaGetSymbolAddress((void**)&hS1,  g_hS1);
    uint2* WihS1 = WihS + (size_t)N3 * KP;
    uint2* WhhS1 = WhhS + (size_t)N3 * KP;

    cudaFuncSetAttribute(gru_recurrence,
                         cudaFuncAttributeMaxDynamicSharedMemorySize, REC_SMEM);
    cudaFuncSetAttribute(gemm_xg,
                         cudaFuncAttributeMaxDynamicSharedMemorySize, XG_SMEM);

    dim3 blk(256);
    const int WPAIRS = N3 * KP;               // 1.57M pairs per weight matrix
    const int INPAIRS = MFULL * KP;           // 25.2M pairs
    const int HPAIRS = BB * KP;               // 64K pairs

    // prep: one-time splits
    split_pairs<<<(INPAIRS + 255) / 256, blk>>>((const float2*)rand_input, inS, INPAIRS);
    split_pairs<<<(WPAIRS + 255) / 256, blk>>>((const float2*)Wih0, WihS,  WPAIRS);
    split_pairs<<<(WPAIRS + 255) / 256, blk>>>((const float2*)Wih1, WihS1, WPAIRS);
    split_pairs<<<(WPAIRS + 255) / 256, blk>>>((const float2*)Whh0, WhhS,  WPAIRS);
    split_pairs<<<(WPAIRS + 255) / 256, blk>>>((const float2*)Whh1, WhhS1, WPAIRS);

    dim3 grid_xg(N3 / 64, MFULL / 128);       // 48 x 384

    auto run_pass = [&](const uint2* x, const uint2* WihSp, const float* bih,
                        const uint2* WhhSp, const float* bhh, uint2* y) {
        gemm_xg<<<grid_xg, blk, XG_SMEM>>>(x, WihSp, bih, xg);
        gru_recurrence<<<NBLK, blk, REC_SMEM>>>(xg, WhhSp, bhh, hS0, hS1, y);
    };

    // pass 1: layer0 on rand_input, h = h0[0]
    split_pairs<<<(HPAIRS + 255) / 256, blk>>>((const float2*)h0, hS0, HPAIRS);
    run_pass(inS, WihS, bih0, WhhS, bhh0, yAS);

    // pass 2: layer1 on yA, h = h0[1]
    split_pairs<<<(HPAIRS + 255) / 256, blk>>>(
        (const float2*)(h0 + (size_t)BB * HH), hS0, HPAIRS);
    run_pass(yAS, WihS1, bih1, WhhS1, bhh1, yBS);

    // split+concat over T is identity -> yB feeds second run directly
    // pass 3: layer0 on yB, h = 0  (split of 0 is all-zero bits)
    cudaMemsetAsync(hS0, 0, (size_t)HPAIRS * sizeof(uint2));
    run_pass(yBS, WihS, bih0, WhhS, bhh0, yAS);

    // pass 4: layer1 on yA, h = 0 (y not needed)
    cudaMemsetAsync(hS0, 0, (size_t)HPAIRS * sizeof(uint2));
    run_pass(yAS, WihS1, bih1, WhhS1, bhh1, nullptr);

    final_pred<<<BB, blk>>>(hS0, linW, linb, out);
}

// round 11
// speedup vs baseline: 2.9774x; 1.0120x over previous
#include <cuda_runtime.h>
#include <cuda_fp16.h>
#include <math.h>

// ---------------------------------------------------------------------------
// Problem constants
// ---------------------------------------------------------------------------
#define BB    128
#define TT    384
#define HH    1024
#define N3    3072
#define KK    1024
#define KP    (KK/2)        // 512 fp16-pairs per row
#define MFULL (BB*TT)

#define NBLK  128           // persistent recurrence blocks (1/SM)
#define UPB   8             // hidden units per recurrence block
#define HCH   64            // h staging chunk (k elems) -> 32 pairs
#define NCH   (KK/HCH)      // 16 chunks per step

// ---------------------------------------------------------------------------
// Scratch (device globals -- allocation-free per harness rules)
// ---------------------------------------------------------------------------
__device__ float g_xg [(size_t)MFULL * N3];        // 604 MB fp32 input projections
__device__ uint2 g_inS [(size_t)MFULL * KP];       // split rand_input
__device__ uint2 g_yAS [(size_t)MFULL * KP];       // split layer out ping
__device__ uint2 g_yBS [(size_t)MFULL * KP];       // split layer out pong
__device__ uint2 g_WihS[2][(size_t)N3 * KP];       // split Wih
__device__ uint2 g_WhhS[2][(size_t)N3 * KP];       // split Whh
__device__ uint2 g_hS0 [BB * KP];                  // split hidden ping
__device__ uint2 g_hS1 [BB * KP];                  // split hidden pong

// grid barrier (validated R3/R7/R9 semantics)
__device__ volatile unsigned g_barA = 0;
__device__ volatile unsigned g_gen  = 0;

__device__ __forceinline__ void grid_sync(unsigned nb)
{
    __syncthreads();
    if (threadIdx.x == 0) {
        unsigned old = g_gen;
        __threadfence();
        if (atomicAdd((unsigned*)&g_barA, 1u) == nb - 1u) {
            g_barA = 0;
            __threadfence();
            atomicAdd((unsigned*)&g_gen, 1u);
        } else {
            while (g_gen == old) { }
        }
        __threadfence();
    }
    __syncthreads();
}

// ---------------------------------------------------------------------------
// Helpers: fp16 hi/lo split pairs, cp.async, m16n8k16 mma
// ---------------------------------------------------------------------------
__device__ __forceinline__ uint2 splitpair(float x0, float x1)
{
    __half h0 = __float2half_rn(x0), h1 = __float2half_rn(x1);
    float  r0 = x0 - __half2float(h0), r1 = x1 - __half2float(h1);
    __half l0 = __float2half_rn(r0), l1 = __float2half_rn(r1);
    uint2 u;
    u.x = (unsigned)__half_as_ushort(h0) | ((unsigned)__half_as_ushort(h1) << 16);
    u.y = (unsigned)__half_as_ushort(l0) | ((unsigned)__half_as_ushort(l1) << 16);
    return u;
}
__device__ __forceinline__ float lo_f(unsigned u) { return __half2float(__ushort_as_half((unsigned short)(u & 0xFFFF))); }
__device__ __forceinline__ float hi_f(unsigned u) { return __half2float(__ushort_as_half((unsigned short)(u >> 16))); }

__device__ __forceinline__ unsigned sptr(const void* p)
{ return (unsigned)__cvta_generic_to_shared(p); }
__device__ __forceinline__ void cpa16(unsigned d, const void* s)
{ asm volatile("cp.async.cg.shared.global [%0], [%1], 16;" :: "r"(d), "l"(s)); }
#define CP_COMMIT() asm volatile("cp.async.commit_group;")
#define CP_WAIT2()  asm volatile("cp.async.wait_group 2;")
#define CP_WAIT1()  asm volatile("cp.async.wait_group 1;")
#define CP_WAIT0()  asm volatile("cp.async.wait_group 0;")

__device__ __forceinline__ void mma_f16(float* d, unsigned a0, unsigned a1,
                                        unsigned a2, unsigned a3,
                                        unsigned b0, unsigned b1)
{
    asm volatile(
        "mma.sync.aligned.m16n8k16.row.col.f32.f16.f16.f32 "
        "{%0,%1,%2,%3}, {%4,%5,%6,%7}, {%8,%9}, {%0,%1,%2,%3};"
        : "+f"(d[0]), "+f"(d[1]), "+f"(d[2]), "+f"(d[3])
        : "r"(a0), "r"(a1), "r"(a2), "r"(a3), "r"(b0), "r"(b1));
}
// 3xFP16: d += Ahi*Blo + Alo*Bhi + Ahi*Bhi   (uint2 .x=hi-pair, .y=lo-pair)
__device__ __forceinline__ void mma3h(float* d, uint2 A0, uint2 A1, uint2 A2,
                                      uint2 A3, uint2 B0, uint2 B1)
{
    mma_f16(d, A0.x, A1.x, A2.x, A3.x, B0.y, B1.y);
    mma_f16(d, A0.y, A1.y, A2.y, A3.y, B0.x, B1.x);
    mma_f16(d, A0.x, A1.x, A2.x, A3.x, B0.x, B1.x);
}

// ---------------------------------------------------------------------------
// Prep: fp32 -> packed (hi,lo) fp16 pair split
// ---------------------------------------------------------------------------
__global__ __launch_bounds__(256) void split_pairs(
    const float2* __restrict__ src, uint2* __restrict__ dst, int n)
{
    int i = blockIdx.x * blockDim.x + threadIdx.x;
    if (i < n) { float2 v = src[i]; dst[i] = splitpair(v.x, v.y); }
}

// ---------------------------------------------------------------------------
// xg GEMM (fp16-3x): unchanged from R9 (latency hidden by 4 CTAs/SM).
// ---------------------------------------------------------------------------
#define XG_SMEM ((2*(128*16) + 2*(64*16)) * (int)sizeof(uint2))   // 49152 B

__global__ __launch_bounds__(256) void gemm_xg(
    const uint2* __restrict__ A, const uint2* __restrict__ W,
    const float* __restrict__ bias, float* __restrict__ C)
{
    extern __shared__ uint2 smv[];
    uint2* sA[2] = { smv,            smv + 128*16 };
    uint2* sB[2] = { smv + 2*128*16, smv + 2*128*16 + 64*16 };

    const int tid  = threadIdx.x;
    const int lane = tid & 31;
    const int w    = tid >> 5;
    const int wm   = w & 3, wn = w >> 2;
    const int qr   = lane >> 2;
    const int lq   = lane & 3;
    const int m0   = blockIdx.y * 128;
    const int n0   = blockIdx.x * 64;

    float D[2][4][4] = {};

    auto stage = [&](int kc, int s) {
        #pragma unroll
        for (int u = 0; u < 4; ++u) {              // A: 1024 granules
            int gi = tid + u * 256;
            int row = gi >> 3, g = gi & 7;
            const uint2* src = A + (size_t)(m0 + row) * KP + kc * 16 + g * 2;
            int ks = (g * 2) ^ ((row & 3) << 2);
            cpa16(sptr(sA[s] + row * 16 + ks), src);
        }
        #pragma unroll
        for (int u = 0; u < 2; ++u) {              // B: 512 granules
            int gi = tid + u * 256;
            int row = gi >> 3, g = gi & 7;
            const uint2* src = W + (size_t)(n0 + row) * KP + kc * 16 + g * 2;
            int ks = (g * 2) ^ ((row & 3) << 2);
            cpa16(sptr(sB[s] + row * 16 + ks), src);
        }
        CP_COMMIT();
    };

    stage(0, 0);
    for (int kc = 0; kc < 32; ++kc) {
        if (kc < 31) { stage(kc + 1, (kc + 1) & 1); CP_WAIT1(); }
        else         { CP_WAIT0(); }
        __syncthreads();
        const uint2* bA = sA[kc & 1];
        const uint2* bB = sB[kc & 1];

        #pragma unroll
        for (int kt = 0; kt < 2; ++kt) {
            int pb = kt * 8;
            uint2 Bf[4][2];
            #pragma unroll
            for (int fn = 0; fn < 4; ++fn) {
                int nb = wn * 32 + fn * 8 + qr;
                int swz = (nb & 3) << 2;
                Bf[fn][0] = bB[nb * 16 + ((pb + lq) ^ swz)];
                Bf[fn][1] = bB[nb * 16 + ((pb + 4 + lq) ^ swz)];
            }
            #pragma unroll
            for (int f = 0; f < 2; ++f) {
                int ra = wm * 32 + f * 16 + qr;
                int swz = (ra & 3) << 2;
                int k0 = (pb + lq) ^ swz, k1 = (pb + 4 + lq) ^ swz;
                uint2 A0 = bA[ra * 16 + k0];
                uint2 A1 = bA[(ra + 8) * 16 + k0];
                uint2 A2 = bA[ra * 16 + k1];
                uint2 A3 = bA[(ra + 8) * 16 + k1];
                #pragma unroll
                for (int fn = 0; fn < 4; ++fn)
                    mma3h(D[f][fn], A0, A1, A2, A3, Bf[fn][0], Bf[fn][1]);
            }
        }
        __syncthreads();
    }

    #pragma unroll
    for (int f = 0; f < 2; ++f)
        #pragma unroll
        for (int i = 0; i < 2; ++i) {
            int m = m0 + wm * 32 + f * 16 + qr + 8 * i;
            #pragma unroll
            for (int fn = 0; fn < 4; ++fn) {
                int n = n0 + wn * 32 + fn * 8 + (lq << 1);
                float2 bv = *(const float2*)&bias[n];
                float2 o = make_float2(D[f][fn][2*i] + bv.x, D[f][fn][2*i+1] + bv.y);
                *(float2*)&C[(size_t)m * N3 + n] = o;
            }
        }
}

// ---------------------------------------------------------------------------
// Persistent GRU recurrence (fp16-3x mma, split-form state).
// 4-buffer cp.async pipeline over 16 h-chunks, ONE __syncthreads per chunk
// (prefetch distance 3 chunks > L2 latency; tail waits exact).
// smem = 96 KB W + 4 x 32 KB h = 224 KB, 1 block/SM.
// ---------------------------------------------------------------------------
#define SW_U2  (24 * KP)                 // 12288 uint2 = 98304 B
#define SHC_U2 (128 * 32)                // per h chunk: 4096 uint2 = 32768 B
#define REC_SMEM ((SW_U2 + 4 * SHC_U2) * (int)sizeof(uint2))   // 229376 B

__device__ __forceinline__ float sigf(float x) { return 1.0f / (1.0f + expf(-x)); }

__global__ __launch_bounds__(256) void gru_recurrence(
    const float* __restrict__ xg, const uint2* __restrict__ WhhS,
    const float* __restrict__ bhh, uint2* __restrict__ hS0,
    uint2* __restrict__ hS1, uint2* __restrict__ yS)
{
    extern __shared__ uint2 smv[];
    uint2* sW = smv;                              // [24][512] swizzled
    uint2* sH = smv + SW_U2;                      // 4 x [128][32]

    const int tid  = threadIdx.x;
    const int lane = tid & 31;
    const int w    = tid >> 5;
    const int qr   = lane >> 2;
    const int lq   = lane & 3;
    const int j0   = blockIdx.x * UPB;

    // one-time: copy this block's 24 pre-split Whh rows into smem (swizzled)
    for (int idx = tid; idx < 24 * 256; idx += 256) {
        int r = idx >> 8;                 // 0..23 = gate*8+u
        int g = idx & 255;                // granule (2 pairs)
        int gate = r >> 3, u = r & 7;
        const uint2* src = WhhS + (size_t)(gate * HH + j0 + u) * KP + g * 2;
        uint4 v = *(const uint4*)src;
        int ks = (g * 2) ^ ((r & 3) << 2);
        sW[r * KP + ks]     = make_uint2(v.x, v.y);
        sW[r * KP + ks + 1] = make_uint2(v.z, v.w);
    }
    const int qcol = lq << 1;
    const float brj0 = bhh[j0 + qcol],        brj1 = bhh[j0 + qcol + 1];
    const float bzj0 = bhh[HH + j0 + qcol],   bzj1 = bhh[HH + j0 + qcol + 1];
    const float bnj0 = bhh[2*HH + j0 + qcol], bnj1 = bhh[2*HH + j0 + qcol + 1];
    __syncthreads();

    const uint2* hin  = hS0;
    uint2*       hout = hS1;

    for (int t = 0; t < TT; ++t) {
        float Dr[4] = {}, Dz[4] = {}, Dn[4] = {};

        auto stageH = [&](int c) {
            uint2* buf = sH + (c & 3) * SHC_U2;
            #pragma unroll
            for (int u = 0; u < 8; ++u) {          // 2048 granules
                int gi = tid + u * 256;
                int row = gi >> 4, g = gi & 15;
                const uint2* src = hin + (size_t)row * KP + c * 32 + g * 2;
                int ks = (g * 2) ^ ((row & 3) << 2);
                cpa16(sptr(buf + row * 32 + ks), src);
            }
            CP_COMMIT();
        };

        // prime pipeline: chunks 0,1,2 (buffers held last step's chunks
        // 12,13,14 -- consumed before the grid barrier, safe to overwrite)
        stageH(0); stageH(1); stageH(2);

        for (int c = 0; c < NCH; ++c) {
            // exact tail waits: guarantee group c complete
            if      (c < NCH - 2) CP_WAIT2();
            else if (c == NCH - 2) CP_WAIT1();
            else                   CP_WAIT0();
            __syncthreads();               // publish buffer c; all warps done with chunk c-1
            if (c + 3 < NCH) stageH(c + 3);   // overwrites buffer of chunk c-1 (safe)

            const uint2* bH = sH + (c & 3) * SHC_U2;
            #pragma unroll
            for (int kt = 0; kt < 4; ++kt) {
                int pb = kt * 8;
                int ra = 16 * w + qr;
                int swzA = (ra & 3) << 2;
                int k0 = (pb + lq) ^ swzA, k1 = (pb + 4 + lq) ^ swzA;
                uint2 A0 = bH[ra * 32 + k0];
                uint2 A1 = bH[(ra + 8) * 32 + k0];
                uint2 A2 = bH[ra * 32 + k1];
                uint2 A3 = bH[(ra + 8) * 32 + k1];

                int pW = c * 32 + pb;
                {
                    int r = 0 * 8 + qr, swz = (r & 3) << 2;
                    mma3h(Dr, A0, A1, A2, A3,
                          sW[r * KP + ((pW + lq) ^ swz)],
                          sW[r * KP + ((pW + 4 + lq) ^ swz)]);
                }
                {
                    int r = 1 * 8 + qr, swz = (r & 3) << 2;
                    mma3h(Dz, A0, A1, A2, A3,
                          sW[r * KP + ((pW + lq) ^ swz)],
                          sW[r * KP + ((pW + 4 + lq) ^ swz)]);
                }
                {
                    int r = 2 * 8 + qr, swz = (r & 3) << 2;
                    mma3h(Dn, A0, A1, A2, A3,
                          sW[r * KP + ((pW + lq) ^ swz)],
                          sW[r * KP + ((pW + 4 + lq) ^ swz)]);
                }
            }
        }

        // gates: thread owns batches {16w+qr, +8} x unit pair (j0+2lq, j0+2lq+1)
        const int pidx = (j0 >> 1) + lq;
        #pragma unroll
        for (int i = 0; i < 2; ++i) {
            const int b = 16 * w + qr + 8 * i;
            const size_t xo = ((size_t)b * TT + t) * N3 + j0 + qcol;
            float2 xr = *(const float2*)&xg[xo];
            float2 xz = *(const float2*)&xg[xo + HH];
            float2 xn = *(const float2*)&xg[xo + 2 * HH];
            uint2  hs = hin[(size_t)b * KP + pidx];
            float hp0 = lo_f(hs.x) + lo_f(hs.y);
            float hp1 = hi_f(hs.x) + hi_f(hs.y);

            float r0 = sigf(xr.x + Dr[2*i]   + brj0);
            float r1 = sigf(xr.y + Dr[2*i+1] + brj1);
            float z0 = sigf(xz.x + Dz[2*i]   + bzj0);
            float z1 = sigf(xz.y + Dz[2*i+1] + bzj1);
            float n0 = tanhf(xn.x + r0 * (Dn[2*i]   + bnj0));
            float n1 = tanhf(xn.y + r1 * (Dn[2*i+1] + bnj1));
            float h0 = (1.0f - z0) * n0 + z0 * hp0;
            float h1 = (1.0f - z1) * n1 + z1 * hp1;
            uint2 pk = splitpair(h0, h1);
            hout[(size_t)b * KP + pidx] = pk;
            if (yS) yS[((size_t)b * TT + t) * KP + pidx] = pk;
        }

        grid_sync(NBLK);
        const uint2* tmp = hin; hin = hout; hout = (uint2*)tmp;
    }
    // TT even -> final hidden ends in hS0
}

// ---------------------------------------------------------------------------
// predictions[b] = dot(h[b,:], lin_W) + lin_b   (h reconstructed hi+lo)
// ---------------------------------------------------------------------------
__global__ __launch_bounds__(256) void final_pred(
    const uint2* __restrict__ hS, const float* __restrict__ W,
    const float* __restrict__ bias, float* __restrict__ out)
{
    int b = blockIdx.x;
    float s = 0.f;
    for (int p = threadIdx.x; p < KP; p += 256) {
        uint2 u = hS[(size_t)b * KP + p];
        s += (lo_f(u.x) + lo_f(u.y)) * W[2 * p]
           + (hi_f(u.x) + hi_f(u.y)) * W[2 * p + 1];
    }
    #pragma unroll
    for (int o = 16; o; o >>= 1) s += __shfl_xor_sync(0xFFFFFFFFu, s, o);
    __shared__ float ws[8];
    if ((threadIdx.x & 31) == 0) ws[threadIdx.x >> 5] = s;
    __syncthreads();
    if (threadIdx.x == 0) {
        float t = 0.f;
        #pragma unroll
        for (int k = 0; k < 8; ++k) t += ws[k];
        out[b] = t + bias[0];
    }
}

// ---------------------------------------------------------------------------
// Launch — ~20 graph nodes
// ---------------------------------------------------------------------------
extern "C" void kernel_launch(void* const* d_in, const int* in_sizes, int n_in,
                              void* d_out, int out_size)
{
    const float* rand_input = (const float*)d_in[1];
    const float* h0   = (const float*)d_in[2];
    const float* Wih0 = (const float*)d_in[7];
    const float* Whh0 = (const float*)d_in[8];
    const float* bih0 = (const float*)d_in[9];
    const float* bhh0 = (const float*)d_in[10];
    const float* Wih1 = (const float*)d_in[11];
    const float* Whh1 = (const float*)d_in[12];
    const float* bih1 = (const float*)d_in[13];
    const float* bhh1 = (const float*)d_in[14];
    const float* linW = (const float*)d_in[15];
    const float* linb = (const float*)d_in[16];
    float* out = (float*)d_out;

    float *xg;
    uint2 *inS, *yAS, *yBS, *WihS, *WhhS, *hS0, *hS1;
    cudaGetSymbolAddress((void**)&xg,   g_xg);
    cudaGetSymbolAddress((void**)&inS,  g_inS);
    cudaGetSymbolAddress((void**)&yAS,  g_yAS);
    cudaGetSymbolAddress((void**)&yBS,  g_yBS);
    cudaGetSymbolAddress((void**)&WihS, g_WihS);
    cudaGetSymbolAddress((void**)&WhhS, g_WhhS);
    cudaGetSymbolAddress((void**)&hS0,  g_hS0);
    cudaGetSymbolAddress((void**)&hS1,  g_hS1);
    uint2* WihS1 = WihS + (size_t)N3 * KP;
    uint2* WhhS1 = WhhS + (size_t)N3 * KP;

    cudaFuncSetAttribute(gru_recurrence,
                         cudaFuncAttributeMaxDynamicSharedMemorySize, REC_SMEM);
    cudaFuncSetAttribute(gemm_xg,
                         cudaFuncAttributeMaxDynamicSharedMemorySize, XG_SMEM);

    dim3 blk(256);
    const int WPAIRS = N3 * KP;               // 1.57M pairs per weight matrix
    const int INPAIRS = MFULL * KP;           // 25.2M pairs
    const int HPAIRS = BB * KP;               // 64K pairs

    // prep: one-time splits
    split_pairs<<<(INPAIRS + 255) / 256, blk>>>((const float2*)rand_input, inS, INPAIRS);
    split_pairs<<<(WPAIRS + 255) / 256, blk>>>((const float2*)Wih0, WihS,  WPAIRS);
    split_pairs<<<(WPAIRS + 255) / 256, blk>>>((const float2*)Wih1, WihS1, WPAIRS);
    split_pairs<<<(WPAIRS + 255) / 256, blk>>>((const float2*)Whh0, WhhS,  WPAIRS);
    split_pairs<<<(WPAIRS + 255) / 256, blk>>>((const float2*)Whh1, WhhS1, WPAIRS);

    dim3 grid_xg(N3 / 64, MFULL / 128);       // 48 x 384

    auto run_pass = [&](const uint2* x, const uint2* WihSp, const float* bih,
                        const uint2* WhhSp, const float* bhh, uint2* y) {
        gemm_xg<<<grid_xg, blk, XG_SMEM>>>(x, WihSp, bih, xg);
        gru_recurrence<<<NBLK, blk, REC_SMEM>>>(xg, WhhSp, bhh, hS0, hS1, y);
    };

    // pass 1: layer0 on rand_input, h = h0[0]
    split_pairs<<<(HPAIRS + 255) / 256, blk>>>((const float2*)h0, hS0, HPAIRS);
    run_pass(inS, WihS, bih0, WhhS, bhh0, yAS);

    // pass 2: layer1 on yA, h = h0[1]
    split_pairs<<<(HPAIRS + 255) / 256, blk>>>(
        (const float2*)(h0 + (size_t)BB * HH), hS0, HPAIRS);
    run_pass(yAS, WihS1, bih1, WhhS1, bhh1, yBS);

    // split+concat over T is identity -> yB feeds second run directly
    // pass 3: layer0 on yB, h = 0  (split of 0 is all-zero bits)
    cudaMemsetAsync(hS0, 0, (size_t)HPAIRS * sizeof(uint2));
    run_pass(yBS, WihS, bih0, WhhS, bhh0, yAS);

    // pass 4: layer1 on yA, h = 0 (y not needed)
    cudaMemsetAsync(hS0, 0, (size_t)HPAIRS * sizeof(uint2));
    run_pass(yAS, WihS1, bih1, WhhS1, bhh1, nullptr);

    final_pred<<<BB, blk>>>(hS0, linW, linb, out);
}

// round 14
// speedup vs baseline: 3.0185x; 1.0138x over previous
#include <cuda_runtime.h>
#include <cuda_fp16.h>
#include <math.h>

// ---------------------------------------------------------------------------
// Problem constants
// ---------------------------------------------------------------------------
#define BB    128
#define TT    384
#define HH    1024
#define N3    3072
#define KK    1024
#define KP    (KK/2)        // 512 fp16-pairs per row
#define MFULL (BB*TT)

#define NBLK  128           // persistent recurrence blocks (1/SM)
#define UPB   8             // hidden units per recurrence block
#define NCH   16            // h chunks per step (64 elems each)

#define WPAIRS  (N3*KP)     // 1,572,864 pairs per weight matrix
#define INPAIRS (MFULL*KP)  // 25,165,824 pairs
#define HPAIRS  (BB*KP)     // 65,536 pairs

// ---------------------------------------------------------------------------
// Scratch (device globals -- allocation-free per harness rules)
// ---------------------------------------------------------------------------
__device__ float g_xg [(size_t)MFULL * N3];        // fp32 input projections
__device__ uint2 g_inS [(size_t)MFULL * KP];       // split rand_input
__device__ uint2 g_yAS [(size_t)MFULL * KP];       // split layer out ping
__device__ uint2 g_yBS [(size_t)MFULL * KP];       // split layer out pong
__device__ uint2 g_WihS[2][(size_t)N3 * KP];       // split Wih (L0, L1)
__device__ uint2 g_WhhS[2][(size_t)N3 * KP];       // split Whh (L0, L1)
__device__ uint2 g_hA  [BB * KP];                  // h0 layer0 / pass3 init
__device__ uint2 g_hB  [BB * KP];                  // h0 layer1 / pass4 init
__device__ uint2 g_hC  [BB * KP];                  // ping-pong scratch

// ---------------------------------------------------------------------------
// Tree grid barrier: 16-wide groups -> 8-wide root, monotonic counters
// (no resets; survives graph replays). Poll with nanosleep backoff.
// ---------------------------------------------------------------------------
__device__ unsigned g_grp[8 * 64];     // 256 B stride between group counters
__device__ unsigned g_root = 0;
__device__ volatile unsigned g_gen = 0;

__device__ __forceinline__ void grid_sync(unsigned /*nb*/)
{
    __syncthreads();
    if (threadIdx.x == 0) {
        unsigned old = g_gen;
        __threadfence();                               // release prior writes
        unsigned o = atomicAdd(&g_grp[(blockIdx.x >> 4) * 64], 1u);
        if ((o & 15u) == 15u) {                        // last in group
            unsigned r = atomicAdd(&g_root, 1u);
            if ((r & 7u) == 7u)                        // last group
                atomicAdd((unsigned*)&g_gen, 1u);      // open gate
        }
        while (g_gen == old) __nanosleep(64);
        __threadfence();                               // acquire
    }
    __syncthreads();
}

// ---------------------------------------------------------------------------
// Helpers: fp16 hi/lo split pairs, cp.async, m16n8k16 mma
// ---------------------------------------------------------------------------
__device__ __forceinline__ uint2 splitpair(float x0, float x1)
{
    __half h0 = __float2half_rn(x0), h1 = __float2half_rn(x1);
    float  r0 = x0 - __half2float(h0), r1 = x1 - __half2float(h1);
    __half l0 = __float2half_rn(r0), l1 = __float2half_rn(r1);
    uint2 u;
    u.x = (unsigned)__half_as_ushort(h0) | ((unsigned)__half_as_ushort(h1) << 16);
    u.y = (unsigned)__half_as_ushort(l0) | ((unsigned)__half_as_ushort(l1) << 16);
    return u;
}
__device__ __forceinline__ float lo_f(unsigned u) { return __half2float(__ushort_as_half((unsigned short)(u & 0xFFFF))); }
__device__ __forceinline__ float hi_f(unsigned u) { return __half2float(__ushort_as_half((unsigned short)(u >> 16))); }

__device__ __forceinline__ unsigned sptr(const void* p)
{ return (unsigned)__cvta_generic_to_shared(p); }
__device__ __forceinline__ void cpa16(unsigned d, const void* s)
{ asm volatile("cp.async.cg.shared.global [%0], [%1], 16;" :: "r"(d), "l"(s)); }
#define CP_COMMIT() asm volatile("cp.async.commit_group;")
#define CP_WAIT2()  asm volatile("cp.async.wait_group 2;")
#define CP_WAIT1()  asm volatile("cp.async.wait_group 1;")
#define CP_WAIT0()  asm volatile("cp.async.wait_group 0;")

__device__ __forceinline__ void mma_f16(float* d, unsigned a0, unsigned a1,
                                        unsigned a2, unsigned a3,
                                        unsigned b0, unsigned b1)
{
    asm volatile(
        "mma.sync.aligned.m16n8k16.row.col.f32.f16.f16.f32 "
        "{%0,%1,%2,%3}, {%4,%5,%6,%7}, {%8,%9}, {%0,%1,%2,%3};"
        : "+f"(d[0]), "+f"(d[1]), "+f"(d[2]), "+f"(d[3])
        : "r"(a0), "r"(a1), "r"(a2), "r"(a3), "r"(b0), "r"(b1));
}
// 3xFP16: d += Ahi*Blo + Alo*Bhi + Ahi*Bhi
__device__ __forceinline__ void mma3h(float* d, uint2 A0, uint2 A1, uint2 A2,
                                      uint2 A3, uint2 B0, uint2 B1)
{
    mma_f16(d, A0.x, A1.x, A2.x, A3.x, B0.y, B1.y);
    mma_f16(d, A0.y, A1.y, A2.y, A3.y, B0.x, B1.x);
    mma_f16(d, A0.x, A1.x, A2.x, A3.x, B0.x, B1.x);
}

// ---------------------------------------------------------------------------
// Prep kernel 1: split rand_input + both h0 layers (one launch)
// ---------------------------------------------------------------------------
__global__ __launch_bounds__(256) void prep_misc(
    const float2* __restrict__ rin, const float2* __restrict__ h0,
    uint2* __restrict__ inS, uint2* __restrict__ hA, uint2* __restrict__ hB)
{
    int i = blockIdx.x * 256 + threadIdx.x;
    if (i < INPAIRS) {
        float2 v = rin[i]; inS[i] = splitpair(v.x, v.y); return;
    }
    i -= INPAIRS;
    if (i < HPAIRS) {
        float2 v = h0[i]; hA[i] = splitpair(v.x, v.y); return;
    }
    i -= HPAIRS;
    if (i < HPAIRS) {
        float2 v = h0[HPAIRS + i]; hB[i] = splitpair(v.x, v.y);
    }
}

// ---------------------------------------------------------------------------
// Prep kernel 2: split all 4 weight matrices (one launch)
// ---------------------------------------------------------------------------
__global__ __launch_bounds__(256) void prep_weights(
    const float2* __restrict__ w0, const float2* __restrict__ w1,
    const float2* __restrict__ w2, const float2* __restrict__ w3,
    uint2* __restrict__ d0, uint2* __restrict__ d1,
    uint2* __restrict__ d2, uint2* __restrict__ d3)
{
    int i = blockIdx.x * 256 + threadIdx.x;
    if (i >= 4 * WPAIRS) return;
    int m = i / WPAIRS, r = i - m * WPAIRS;
    const float2* s = (m == 0) ? w0 : (m == 1) ? w1 : (m == 2) ? w2 : w3;
    uint2*        d = (m == 0) ? d0 : (m == 1) ? d1 : (m == 2) ? d2 : d3;
    float2 v = s[r];
    d[r] = splitpair(v.x, v.y);
}

// ---------------------------------------------------------------------------
// xg GEMM (fp16-3x): identical to the R11 kernel that measured 43.7 ms.
// ---------------------------------------------------------------------------
#define XG_SMEM ((2*(128*16) + 2*(64*16)) * (int)sizeof(uint2))   // 49152 B

__global__ __launch_bounds__(256) void gemm_xg(
    const uint2* __restrict__ A, const uint2* __restrict__ W,
    const float* __restrict__ bias, float* __restrict__ C)
{
    extern __shared__ uint2 smv[];
    uint2* sA[2] = { smv,            smv + 128*16 };
    uint2* sB[2] = { smv + 2*128*16, smv + 2*128*16 + 64*16 };

    const int tid  = threadIdx.x;
    const int lane = tid & 31;
    const int w    = tid >> 5;
    const int wm   = w & 3, wn = w >> 2;
    const int qr   = lane >> 2;
    const int lq   = lane & 3;
    const int m0   = blockIdx.y * 128;
    const int n0   = blockIdx.x * 64;

    float D[2][4][4] = {};

    auto stage = [&](int kc, int s) {
        #pragma unroll
        for (int u = 0; u < 4; ++u) {
            int gi = tid + u * 256;
            int row = gi >> 3, g = gi & 7;
            const uint2* src = A + (size_t)(m0 + row) * KP + kc * 16 + g * 2;
            int ks = (g * 2) ^ ((row & 3) << 2);
            cpa16(sptr(sA[s] + row * 16 + ks), src);
        }
        #pragma unroll
        for (int u = 0; u < 2; ++u) {
            int gi = tid + u * 256;
            int row = gi >> 3, g = gi & 7;
            const uint2* src = W + (size_t)(n0 + row) * KP + kc * 16 + g * 2;
            int ks = (g * 2) ^ ((row & 3) << 2);
            cpa16(sptr(sB[s] + row * 16 + ks), src);
        }
        CP_COMMIT();
    };

    stage(0, 0);
    for (int kc = 0; kc < 32; ++kc) {
        if (kc < 31) { stage(kc + 1, (kc + 1) & 1); CP_WAIT1(); }
        else         { CP_WAIT0(); }
        __syncthreads();
        const uint2* bA = sA[kc & 1];
        const uint2* bB = sB[kc & 1];

        #pragma unroll
        for (int kt = 0; kt < 2; ++kt) {
            int pb = kt * 8;
            uint2 Bf[4][2];
            #pragma unroll
            for (int fn = 0; fn < 4; ++fn) {
                int nb = wn * 32 + fn * 8 + qr;
                int swz = (nb & 3) << 2;
                Bf[fn][0] = bB[nb * 16 + ((pb + lq) ^ swz)];
                Bf[fn][1] = bB[nb * 16 + ((pb + 4 + lq) ^ swz)];
            }
            #pragma unroll
            for (int f = 0; f < 2; ++f) {
                int ra = wm * 32 + f * 16 + qr;
                int swz = (ra & 3) << 2;
                int k0 = (pb + lq) ^ swz, k1 = (pb + 4 + lq) ^ swz;
                uint2 A0 = bA[ra * 16 + k0];
                uint2 A1 = bA[(ra + 8) * 16 + k0];
                uint2 A2 = bA[ra * 16 + k1];
                uint2 A3 = bA[(ra + 8) * 16 + k1];
                #pragma unroll
                for (int fn = 0; fn < 4; ++fn)
                    mma3h(D[f][fn], A0, A1, A2, A3, Bf[fn][0], Bf[fn][1]);
            }
        }
        __syncthreads();
    }

    #pragma unroll
    for (int f = 0; f < 2; ++f)
        #pragma unroll
        for (int i = 0; i < 2; ++i) {
            int m = m0 + wm * 32 + f * 16 + qr + 8 * i;
            #pragma unroll
            for (int fn = 0; fn < 4; ++fn) {
                int n = n0 + wn * 32 + fn * 8 + (lq << 1);
                float2 bv = *(const float2*)&bias[n];
                float2 o = make_float2(D[f][fn][2*i] + bv.x, D[f][fn][2*i+1] + bv.y);
                *(float2*)&C[(size_t)m * N3 + n] = o;
            }
        }
}

// ---------------------------------------------------------------------------
// Persistent GRU recurrence: identical compute to R11 (4-buffer cp.async
// pipeline, fp16-3x mma, split-form state); only the barrier changed.
// ---------------------------------------------------------------------------
#define SW_U2  (24 * KP)                 // 12288 uint2 = 98304 B
#define SHC_U2 (128 * 32)                // per h chunk: 4096 uint2 = 32768 B
#define REC_SMEM ((SW_U2 + 4 * SHC_U2) * (int)sizeof(uint2))   // 229376 B

__device__ __forceinline__ float sigf(float x) { return 1.0f / (1.0f + expf(-x)); }

__global__ __launch_bounds__(256) void gru_recurrence(
    const float* __restrict__ xg, const uint2* __restrict__ WhhS,
    const float* __restrict__ bhh, uint2* __restrict__ hS0,
    uint2* __restrict__ hS1, uint2* __restrict__ yS)
{
    extern __shared__ uint2 smv[];
    uint2* sW = smv;                              // [24][512] swizzled
    uint2* sH = smv + SW_U2;                      // 4 x [128][32]

    const int tid  = threadIdx.x;
    const int lane = tid & 31;
    const int w    = tid >> 5;
    const int qr   = lane >> 2;
    const int lq   = lane & 3;
    const int j0   = blockIdx.x * UPB;

    // one-time: copy this block's 24 pre-split Whh rows into smem (swizzled)
    for (int idx = tid; idx < 24 * 256; idx += 256) {
        int r = idx >> 8;                 // 0..23 = gate*8+u
        int g = idx & 255;                // granule (2 pairs)
        int gate = r >> 3, u = r & 7;
        const uint2* src = WhhS + (size_t)(gate * HH + j0 + u) * KP + g * 2;
        uint4 v = *(const uint4*)src;
        int ks = (g * 2) ^ ((r & 3) << 2);
        sW[r * KP + ks]     = make_uint2(v.x, v.y);
        sW[r * KP + ks + 1] = make_uint2(v.z, v.w);
    }
    const int qcol = lq << 1;
    const float brj0 = bhh[j0 + qcol],        brj1 = bhh[j0 + qcol + 1];
    const float bzj0 = bhh[HH + j0 + qcol],   bzj1 = bhh[HH + j0 + qcol + 1];
    const float bnj0 = bhh[2*HH + j0 + qcol], bnj1 = bhh[2*HH + j0 + qcol + 1];
    __syncthreads();

    const uint2* hin  = hS0;
    uint2*       hout = hS1;

    for (int t = 0; t < TT; ++t) {
        float Dr[4] = {}, Dz[4] = {}, Dn[4] = {};

        auto stageH = [&](int c) {
            uint2* buf = sH + (c & 3) * SHC_U2;
            #pragma unroll
            for (int u = 0; u < 8; ++u) {
                int gi = tid + u * 256;
                int row = gi >> 4, g = gi & 15;
                const uint2* src = hin + (size_t)row * KP + c * 32 + g * 2;
                int ks = (g * 2) ^ ((row & 3) << 2);
                cpa16(sptr(buf + row * 32 + ks), src);
            }
            CP_COMMIT();
        };

        stageH(0); stageH(1); stageH(2);

        for (int c = 0; c < NCH; ++c) {
            if      (c < NCH - 2)  CP_WAIT2();
            else if (c == NCH - 2) CP_WAIT1();
            else                   CP_WAIT0();
            __syncthreads();
            if (c + 3 < NCH) stageH(c + 3);

            const uint2* bH = sH + (c & 3) * SHC_U2;
            #pragma unroll
            for (int kt = 0; kt < 4; ++kt) {
                int pb = kt * 8;
                int ra = 16 * w + qr;
                int swzA = (ra & 3) << 2;
                int k0 = (pb + lq) ^ swzA, k1 = (pb + 4 + lq) ^ swzA;
                uint2 A0 = bH[ra * 32 + k0];
                uint2 A1 = bH[(ra + 8) * 32 + k0];
                uint2 A2 = bH[ra * 32 + k1];
                uint2 A3 = bH[(ra + 8) * 32 + k1];

                int pW = c * 32 + pb;
                {
                    int r = 0 * 8 + qr, swz = (r & 3) << 2;
                    mma3h(Dr, A0, A1, A2, A3,
                          sW[r * KP + ((pW + lq) ^ swz)],
                          sW[r * KP + ((pW + 4 + lq) ^ swz)]);
                }
                {
                    int r = 1 * 8 + qr, swz = (r & 3) << 2;
                    mma3h(Dz, A0, A1, A2, A3,
                          sW[r * KP + ((pW + lq) ^ swz)],
                          sW[r * KP + ((pW + 4 + lq) ^ swz)]);
                }
                {
                    int r = 2 * 8 + qr, swz = (r & 3) << 2;
                    mma3h(Dn, A0, A1, A2, A3,
                          sW[r * KP + ((pW + lq) ^ swz)],
                          sW[r * KP + ((pW + 4 + lq) ^ swz)]);
                }
            }
        }

        // gates
        const int pidx = (j0 >> 1) + lq;
        #pragma unroll
        for (int i = 0; i < 2; ++i) {
            const int b = 16 * w + qr + 8 * i;
            const size_t xo = ((size_t)b * TT + t) * N3 + j0 + qcol;
            float2 xr = *(const float2*)&xg[xo];
            float2 xz = *(const float2*)&xg[xo + HH];
            float2 xn = *(const float2*)&xg[xo + 2 * HH];
            uint2  hs = hin[(size_t)b * KP + pidx];
            float hp0 = lo_f(hs.x) + lo_f(hs.y);
            float hp1 = hi_f(hs.x) + hi_f(hs.y);

            float r0 = sigf(xr.x + Dr[2*i]   + brj0);
            float r1 = sigf(xr.y + Dr[2*i+1] + brj1);
            float z0 = sigf(xz.x + Dz[2*i]   + bzj0);
            float z1 = sigf(xz.y + Dz[2*i+1] + bzj1);
            float n0 = tanhf(xn.x + r0 * (Dn[2*i]   + bnj0));
            float n1 = tanhf(xn.y + r1 * (Dn[2*i+1] + bnj1));
            float h0 = (1.0f - z0) * n0 + z0 * hp0;
            float h1 = (1.0f - z1) * n1 + z1 * hp1;
            uint2 pk = splitpair(h0, h1);
            hout[(size_t)b * KP + pidx] = pk;
            if (yS) yS[((size_t)b * TT + t) * KP + pidx] = pk;
        }

        grid_sync(NBLK);
        const uint2* tmp = hin; hin = hout; hout = (uint2*)tmp;
    }
    // TT even -> final hidden ends in hS0 (the initial buffer)
}

// ---------------------------------------------------------------------------
// predictions[b] = dot(h[b,:], lin_W) + lin_b
// ---------------------------------------------------------------------------
__global__ __launch_bounds__(256) void final_pred(
    const uint2* __restrict__ hS, const float* __restrict__ W,
    const float* __restrict__ bias, float* __restrict__ out)
{
    int b = blockIdx.x;
    float s = 0.f;
    for (int p = threadIdx.x; p < KP; p += 256) {
        uint2 u = hS[(size_t)b * KP + p];
        s += (lo_f(u.x) + lo_f(u.y)) * W[2 * p]
           + (hi_f(u.x) + hi_f(u.y)) * W[2 * p + 1];
    }
    #pragma unroll
    for (int o = 16; o; o >>= 1) s += __shfl_xor_sync(0xFFFFFFFFu, s, o);
    __shared__ float ws[8];
    if ((threadIdx.x & 31) == 0) ws[threadIdx.x >> 5] = s;
    __syncthreads();
    if (threadIdx.x == 0) {
        float t = 0.f;
        #pragma unroll
        for (int k = 0; k < 8; ++k) t += ws[k];
        out[b] = t + bias[0];
    }
}

// ---------------------------------------------------------------------------
// Launch — prep fused to 2 kernels so ncu (-s 5 -c 1) lands on
// gru_recurrence: [0] prep_misc [1] prep_weights [2] gemm [3] recur
// [4] gemm [5] recur <- profiled
// ---------------------------------------------------------------------------
extern "C" void kernel_launch(void* const* d_in, const int* in_sizes, int n_in,
                              void* d_out, int out_size)
{
    const float* rand_input = (const float*)d_in[1];
    const float* h0   = (const float*)d_in[2];
    const float* Wih0 = (const float*)d_in[7];
    const float* Whh0 = (const float*)d_in[8];
    const float* bih0 = (const float*)d_in[9];
    const float* bhh0 = (const float*)d_in[10];
    const float* Wih1 = (const float*)d_in[11];
    const float* Whh1 = (const float*)d_in[12];
    const float* bih1 = (const float*)d_in[13];
    const float* bhh1 = (const float*)d_in[14];
    const float* linW = (const float*)d_in[15];
    const float* linb = (const float*)d_in[16];
    float* out = (float*)d_out;

    float *xg;
    uint2 *inS, *yAS, *yBS, *WihS, *WhhS, *hA, *hB, *hC;
    cudaGetSymbolAddress((void**)&xg,   g_xg);
    cudaGetSymbolAddress((void**)&inS,  g_inS);
    cudaGetSymbolAddress((void**)&yAS,  g_yAS);
    cudaGetSymbolAddress((void**)&yBS,  g_yBS);
    cudaGetSymbolAddress((void**)&WihS, g_WihS);
    cudaGetSymbolAddress((void**)&WhhS, g_WhhS);
    cudaGetSymbolAddress((void**)&hA,   g_hA);
    cudaGetSymbolAddress((void**)&hB,   g_hB);
    cudaGetSymbolAddress((void**)&hC,   g_hC);
    uint2* WihS1 = WihS + (size_t)N3 * KP;
    uint2* WhhS1 = WhhS + (size_t)N3 * KP;

    cudaFuncSetAttribute(gru_recurrence,
                         cudaFuncAttributeMaxDynamicSharedMemorySize, REC_SMEM);
    cudaFuncSetAttribute(gemm_xg,
                         cudaFuncAttributeMaxDynamicSharedMemorySize, XG_SMEM);

    dim3 blk(256);
    dim3 grid_xg(N3 / 64, MFULL / 128);       // 48 x 384

    // [0] prep: rand_input + both h0 layers
    prep_misc<<<(INPAIRS + 2 * HPAIRS + 255) / 256, blk>>>(
        (const float2*)rand_input, (const float2*)h0, inS, hA, hB);
    // [1] prep: all 4 weight matrices
    prep_weights<<<(4 * WPAIRS + 255) / 256, blk>>>(
        (const float2*)Wih0, (const float2*)Whh0,
        (const float2*)Wih1, (const float2*)Whh1,
        WihS, WhhS, WihS1, WhhS1);

    auto run_pass = [&](const uint2* x, const uint2* WihSp, const float* bih,
                        const uint2* WhhSp, const float* bhh,
                        uint2* h_init, uint2* y) {
        gemm_xg<<<grid_xg, blk, XG_SMEM>>>(x, WihSp, bih, xg);
        gru_recurrence<<<NBLK, blk, REC_SMEM>>>(xg, WhhSp, bhh, h_init, hC, y);
    };

    // [2,3] pass 1: layer0 on rand_input, h = h0[0] (hA)
    run_pass(inS, WihS, bih0, WhhS, bhh0, hA, yAS);
    // [4,5] pass 2: layer1 on yA, h = h0[1] (hB)   <- recurrence profiled
    run_pass(yAS, WihS1, bih1, WhhS1, bhh1, hB, yBS);

    // pass 3: layer0 on yB, h = 0
    cudaMemsetAsync(hA, 0, (size_t)HPAIRS * sizeof(uint2));
    run_pass(yBS, WihS, bih0, WhhS, bhh0, hA, yAS);

    // pass 4: layer1 on yA, h = 0 (y not needed)
    cudaMemsetAsync(hB, 0, (size_t)HPAIRS * sizeof(uint2));
    run_pass(yAS, WihS1, bih1, WhhS1, bhh1, hB, nullptr);

    final_pred<<<BB, blk>>>(hB, linW, linb, out);
}

// round 15
// speedup vs baseline: 3.1352x; 1.0387x over previous
#include <cuda_runtime.h>
#include <cuda_fp16.h>
#include <math.h>

// ---------------------------------------------------------------------------
// Problem constants
// ---------------------------------------------------------------------------
#define BB    128
#define TT    384
#define HH    1024
#define N3    3072
#define KK    1024
#define KP    (KK/2)        // 512 fp16-pairs per row
#define MFULL (BB*TT)

#define NBLK  128           // persistent recurrence blocks (1/SM)
#define NCH   16            // h chunks per step (64 elems each)

#define WPAIRS  (N3*KP)     // 1,572,864 pairs per weight matrix
#define INPAIRS (MFULL*KP)  // 25,165,824 pairs
#define HPAIRS  (BB*KP)     // 65,536 pairs

// ---------------------------------------------------------------------------
// Scratch (device globals -- allocation-free per harness rules)
// ---------------------------------------------------------------------------
__device__ float g_xg [(size_t)MFULL * N3];        // fp32 input projections
__device__ uint2 g_inS [(size_t)MFULL * KP];       // split rand_input
__device__ uint2 g_yAS [(size_t)MFULL * KP];       // split layer out ping
__device__ uint2 g_yBS [(size_t)MFULL * KP];       // split layer out pong
__device__ uint2 g_WihS[2][(size_t)N3 * KP];       // split Wih (L0, L1)
__device__ uint2 g_WhhS[2][(size_t)N3 * KP];       // split Whh (L0, L1)
__device__ uint2 g_hA  [BB * KP];                  // h0 layer0 / pass3 init
__device__ uint2 g_hB  [BB * KP];                  // h0 layer1 / pass4 init
__device__ uint2 g_hC  [BB * KP];                  // ping-pong scratch

// ---------------------------------------------------------------------------
// Tree grid barrier (validated R14): 16-wide groups -> 8-wide root,
// monotonic counters, nanosleep backoff.
// ---------------------------------------------------------------------------
__device__ unsigned g_grp[8 * 64];     // 256 B stride between group counters
__device__ unsigned g_root = 0;
__device__ volatile unsigned g_gen = 0;

__device__ __forceinline__ void grid_sync(unsigned /*nb*/)
{
    __syncthreads();
    if (threadIdx.x == 0) {
        unsigned old = g_gen;
        __threadfence();                               // release prior writes
        unsigned o = atomicAdd(&g_grp[(blockIdx.x >> 4) * 64], 1u);
        if ((o & 15u) == 15u) {                        // last in group
            unsigned r = atomicAdd(&g_root, 1u);
            if ((r & 7u) == 7u)                        // last group
                atomicAdd((unsigned*)&g_gen, 1u);      // open gate
        }
        while (g_gen == old) __nanosleep(64);
        __threadfence();                               // acquire
    }
    __syncthreads();
}

// ---------------------------------------------------------------------------
// Helpers: fp16 hi/lo split pairs, cp.async, m16n8k16 mma
// ---------------------------------------------------------------------------
__device__ __forceinline__ uint2 splitpair(float x0, float x1)
{
    __half h0 = __float2half_rn(x0), h1 = __float2half_rn(x1);
    float  r0 = x0 - __half2float(h0), r1 = x1 - __half2float(h1);
    __half l0 = __float2half_rn(r0), l1 = __float2half_rn(r1);
    uint2 u;
    u.x = (unsigned)__half_as_ushort(h0) | ((unsigned)__half_as_ushort(h1) << 16);
    u.y = (unsigned)__half_as_ushort(l0) | ((unsigned)__half_as_ushort(l1) << 16);
    return u;
}
__device__ __forceinline__ float lo_f(unsigned u) { return __half2float(__ushort_as_half((unsigned short)(u & 0xFFFF))); }
__device__ __forceinline__ float hi_f(unsigned u) { return __half2float(__ushort_as_half((unsigned short)(u >> 16))); }

__device__ __forceinline__ unsigned sptr(const void* p)
{ return (unsigned)__cvta_generic_to_shared(p); }
__device__ __forceinline__ void cpa16(unsigned d, const void* s)
{ asm volatile("cp.async.cg.shared.global [%0], [%1], 16;" :: "r"(d), "l"(s)); }
#define CP_COMMIT() asm volatile("cp.async.commit_group;")
#define CP_WAIT1()  asm volatile("cp.async.wait_group 1;")
#define CP_WAIT0()  asm volatile("cp.async.wait_group 0;")

__device__ __forceinline__ void mma_f16(float* d, unsigned a0, unsigned a1,
                                        unsigned a2, unsigned a3,
                                        unsigned b0, unsigned b1)
{
    asm volatile(
        "mma.sync.aligned.m16n8k16.row.col.f32.f16.f16.f32 "
        "{%0,%1,%2,%3}, {%4,%5,%6,%7}, {%8,%9}, {%0,%1,%2,%3};"
        : "+f"(d[0]), "+f"(d[1]), "+f"(d[2]), "+f"(d[3])
        : "r"(a0), "r"(a1), "r"(a2), "r"(a3), "r"(b0), "r"(b1));
}
// 3xFP16: d += Ahi*Blo + Alo*Bhi + Ahi*Bhi
__device__ __forceinline__ void mma3h(float* d, uint2 A0, uint2 A1, uint2 A2,
                                      uint2 A3, uint2 B0, uint2 B1)
{
    mma_f16(d, A0.x, A1.x, A2.x, A3.x, B0.y, B1.y);
    mma_f16(d, A0.y, A1.y, A2.y, A3.y, B0.x, B1.x);
    mma_f16(d, A0.x, A1.x, A2.x, A3.x, B0.x, B1.x);
}

// ---------------------------------------------------------------------------
// Prep kernel 1: split rand_input + both h0 layers (one launch)
// ---------------------------------------------------------------------------
__global__ __launch_bounds__(256) void prep_misc(
    const float2* __restrict__ rin, const float2* __restrict__ h0,
    uint2* __restrict__ inS, uint2* __restrict__ hA, uint2* __restrict__ hB)
{
    int i = blockIdx.x * 256 + threadIdx.x;
    if (i < INPAIRS) {
        float2 v = rin[i]; inS[i] = splitpair(v.x, v.y); return;
    }
    i -= INPAIRS;
    if (i < HPAIRS) {
        float2 v = h0[i]; hA[i] = splitpair(v.x, v.y); return;
    }
    i -= HPAIRS;
    if (i < HPAIRS) {
        float2 v = h0[HPAIRS + i]; hB[i] = splitpair(v.x, v.y);
    }
}

// ---------------------------------------------------------------------------
// Prep kernel 2: split all 4 weight matrices (one launch)
// ---------------------------------------------------------------------------
__global__ __launch_bounds__(256) void prep_weights(
    const float2* __restrict__ w0, const float2* __restrict__ w1,
    const float2* __restrict__ w2, const float2* __restrict__ w3,
    uint2* __restrict__ d0, uint2* __restrict__ d1,
    uint2* __restrict__ d2, uint2* __restrict__ d3)
{
    int i = blockIdx.x * 256 + threadIdx.x;
    if (i >= 4 * WPAIRS) return;
    int m = i / WPAIRS, r = i - m * WPAIRS;
    const float2* s = (m == 0) ? w0 : (m == 1) ? w1 : (m == 2) ? w2 : w3;
    uint2*        d = (m == 0) ? d0 : (m == 1) ? d1 : (m == 2) ? d2 : d3;
    float2 v = s[r];
    d[r] = splitpair(v.x, v.y);
}

// ---------------------------------------------------------------------------
// xg GEMM (fp16-3x): unchanged (measured component of the 43 ms runs).
// ---------------------------------------------------------------------------
#define XG_SMEM ((2*(128*16) + 2*(64*16)) * (int)sizeof(uint2))   // 49152 B

__global__ __launch_bounds__(256) void gemm_xg(
    const uint2* __restrict__ A, const uint2* __restrict__ W,
    const float* __restrict__ bias, float* __restrict__ C)
{
    extern __shared__ uint2 smv[];
    uint2* sA[2] = { smv,            smv + 128*16 };
    uint2* sB[2] = { smv + 2*128*16, smv + 2*128*16 + 64*16 };

    const int tid  = threadIdx.x;
    const int lane = tid & 31;
    const int w    = tid >> 5;
    const int wm   = w & 3, wn = w >> 2;
    const int qr   = lane >> 2;
    const int lq   = lane & 3;
    const int m0   = blockIdx.y * 128;
    const int n0   = blockIdx.x * 64;

    float D[2][4][4] = {};

    auto stage = [&](int kc, int s) {
        #pragma unroll
        for (int u = 0; u < 4; ++u) {
            int gi = tid + u * 256;
            int row = gi >> 3, g = gi & 7;
            const uint2* src = A + (size_t)(m0 + row) * KP + kc * 16 + g * 2;
            int ks = (g * 2) ^ ((row & 3) << 2);
            cpa16(sptr(sA[s] + row * 16 + ks), src);
        }
        #pragma unroll
        for (int u = 0; u < 2; ++u) {
            int gi = tid + u * 256;
            int row = gi >> 3, g = gi & 7;
            const uint2* src = W + (size_t)(n0 + row) * KP + kc * 16 + g * 2;
            int ks = (g * 2) ^ ((row & 3) << 2);
            cpa16(sptr(sB[s] + row * 16 + ks), src);
        }
        CP_COMMIT();
    };

    stage(0, 0);
    for (int kc = 0; kc < 32; ++kc) {
        if (kc < 31) { stage(kc + 1, (kc + 1) & 1); CP_WAIT1(); }
        else         { CP_WAIT0(); }
        __syncthreads();
        const uint2* bA = sA[kc & 1];
        const uint2* bB = sB[kc & 1];

        #pragma unroll
        for (int kt = 0; kt < 2; ++kt) {
            int pb = kt * 8;
            uint2 Bf[4][2];
            #pragma unroll
            for (int fn = 0; fn < 4; ++fn) {
                int nb = wn * 32 + fn * 8 + qr;
                int swz = (nb & 3) << 2;
                Bf[fn][0] = bB[nb * 16 + ((pb + lq) ^ swz)];
                Bf[fn][1] = bB[nb * 16 + ((pb + 4 + lq) ^ swz)];
            }
            #pragma unroll
            for (int f = 0; f < 2; ++f) {
                int ra = wm * 32 + f * 16 + qr;
                int swz = (ra & 3) << 2;
                int k0 = (pb + lq) ^ swz, k1 = (pb + 4 + lq) ^ swz;
                uint2 A0 = bA[ra * 16 + k0];
                uint2 A1 = bA[(ra + 8) * 16 + k0];
                uint2 A2 = bA[ra * 16 + k1];
                uint2 A3 = bA[(ra + 8) * 16 + k1];
                #pragma unroll
                for (int fn = 0; fn < 4; ++fn)
                    mma3h(D[f][fn], A0, A1, A2, A3, Bf[fn][0], Bf[fn][1]);
            }
        }
        __syncthreads();
    }

    #pragma unroll
    for (int f = 0; f < 2; ++f)
        #pragma unroll
        for (int i = 0; i < 2; ++i) {
            int m = m0 + wm * 32 + f * 16 + qr + 8 * i;
            #pragma unroll
            for (int fn = 0; fn < 4; ++fn) {
                int n = n0 + wn * 32 + fn * 8 + (lq << 1);
                float2 bv = *(const float2*)&bias[n];
                float2 o = make_float2(D[f][fn][2*i] + bv.x, D[f][fn][2*i+1] + bv.y);
                *(float2*)&C[(size_t)m * N3 + n] = o;
            }
        }
}

// ---------------------------------------------------------------------------
// Persistent GRU recurrence — R15 re-tiling: block = (batch-half, 16 units).
// Each block stages only 64 h rows per step (h broadcast halved chip-wide:
// 64 -> 32 MB/step) and keeps 48 Whh rows resident (196.6 KB).
// Warps: 4 batch-groups (m16) x 2 unit-groups (n8); 3 gates; fp16-3x mma.
// smem = 196,608 + 2 x 16,384 = 229,376 B (R11-proven footprint), 1 blk/SM.
// ---------------------------------------------------------------------------
#define SW_U2  (48 * KP)                 // 24576 uint2 = 196,608 B
#define SHC_U2 (64 * 32)                 // per h chunk: 2048 uint2 = 16,384 B
#define REC_SMEM ((SW_U2 + 2 * SHC_U2) * (int)sizeof(uint2))   // 229,376 B

__device__ __forceinline__ float sigf(float x) { return 1.0f / (1.0f + expf(-x)); }

__global__ __launch_bounds__(256) void gru_recurrence(
    const float* __restrict__ xg, const uint2* __restrict__ WhhS,
    const float* __restrict__ bhh, uint2* __restrict__ hS0,
    uint2* __restrict__ hS1, uint2* __restrict__ yS)
{
    extern __shared__ uint2 smv[];
    uint2* sW    = smv;                           // [48][512] swizzled
    uint2* sH[2] = { smv + SW_U2, smv + SW_U2 + SHC_U2 };   // [64][32]

    const int tid  = threadIdx.x;
    const int lane = tid & 31;
    const int w    = tid >> 5;
    const int qr   = lane >> 2;
    const int lq   = lane & 3;
    const int wb   = w & 3;               // batch group within block
    const int wu   = w >> 2;              // unit group (0..1)
    const int bb   = blockIdx.x & 1;      // batch half
    const int j0   = (blockIdx.x >> 1) * 16;
    const int b0   = bb * 64;

    // one-time: copy this block's 48 pre-split Whh rows into smem (swizzled)
    for (int idx = tid; idx < 48 * 256; idx += 256) {
        int r = idx >> 8;                 // 0..47 = gate*16+u
        int g = idx & 255;                // granule (2 pairs)
        int gate = r >> 4, u = r & 15;
        const uint2* src = WhhS + (size_t)(gate * HH + j0 + u) * KP + g * 2;
        uint4 v = *(const uint4*)src;
        int ks = (g * 2) ^ ((r & 3) << 2);
        sW[r * KP + ks]     = make_uint2(v.x, v.y);
        sW[r * KP + ks + 1] = make_uint2(v.z, v.w);
    }
    const int qcol = lq << 1;
    const int ucol = wu * 8 + qcol;       // unit offset within the 16
    const float brj0 = bhh[j0 + ucol],        brj1 = bhh[j0 + ucol + 1];
    const float bzj0 = bhh[HH + j0 + ucol],   bzj1 = bhh[HH + j0 + ucol + 1];
    const float bnj0 = bhh[2*HH + j0 + ucol], bnj1 = bhh[2*HH + j0 + ucol + 1];
    __syncthreads();

    const uint2* hin  = hS0;
    uint2*       hout = hS1;

    for (int t = 0; t < TT; ++t) {
        float Dr[4] = {}, Dz[4] = {}, Dn[4] = {};

        auto stageH = [&](int c, int s) {
            uint2* buf = sH[s];
            #pragma unroll
            for (int u = 0; u < 4; ++u) {          // 1024 granules (64 rows)
                int gi = tid + u * 256;
                int row = gi >> 4, g = gi & 15;
                const uint2* src = hin + (size_t)(b0 + row) * KP + c * 32 + g * 2;
                int ks = (g * 2) ^ ((row & 3) << 2);
                cpa16(sptr(buf + row * 32 + ks), src);
            }
            CP_COMMIT();
        };

        stageH(0, 0);
        for (int c = 0; c < NCH; ++c) {
            if (c < NCH - 1) { stageH(c + 1, (c + 1) & 1); CP_WAIT1(); }
            else             { CP_WAIT0(); }
            __syncthreads();
            const uint2* bH = sH[c & 1];

            #pragma unroll
            for (int kt = 0; kt < 4; ++kt) {
                int pb = kt * 8;
                int ra = 16 * wb + qr;            // local h row
                int swzA = (ra & 3) << 2;
                int k0 = (pb + lq) ^ swzA, k1 = (pb + 4 + lq) ^ swzA;
                uint2 A0 = bH[ra * 32 + k0];
                uint2 A1 = bH[(ra + 8) * 32 + k0];
                uint2 A2 = bH[ra * 32 + k1];
                uint2 A3 = bH[(ra + 8) * 32 + k1];

                int pW = c * 32 + pb;
                {
                    int r = 0 * 16 + wu * 8 + qr, swz = (r & 3) << 2;
                    mma3h(Dr, A0, A1, A2, A3,
                          sW[r * KP + ((pW + lq) ^ swz)],
                          sW[r * KP + ((pW + 4 + lq) ^ swz)]);
                }
                {
                    int r = 1 * 16 + wu * 8 + qr, swz = (r & 3) << 2;
                    mma3h(Dz, A0, A1, A2, A3,
                          sW[r * KP + ((pW + lq) ^ swz)],
                          sW[r * KP + ((pW + 4 + lq) ^ swz)]);
                }
                {
                    int r = 2 * 16 + wu * 8 + qr, swz = (r & 3) << 2;
                    mma3h(Dn, A0, A1, A2, A3,
                          sW[r * KP + ((pW + lq) ^ swz)],
                          sW[r * KP + ((pW + 4 + lq) ^ swz)]);
                }
            }
            __syncthreads();
        }

        // gates: thread owns batches {b0+16wb+qr, +8} x units {j0+ucol, +1}
        const int pidx = (j0 >> 1) + wu * 4 + lq;
        #pragma unroll
        for (int i = 0; i < 2; ++i) {
            const int b = b0 + 16 * wb + qr + 8 * i;
            const size_t xo = ((size_t)b * TT + t) * N3 + j0 + ucol;
            float2 xr = *(const float2*)&xg[xo];
            float2 xz = *(const float2*)&xg[xo + HH];
            float2 xn = *(const float2*)&xg[xo + 2 * HH];
            uint2  hs = hin[(size_t)b * KP + pidx];
            float hp0 = lo_f(hs.x) + lo_f(hs.y);
            float hp1 = hi_f(hs.x) + hi_f(hs.y);

            float r0 = sigf(xr.x + Dr[2*i]   + brj0);
            float r1 = sigf(xr.y + Dr[2*i+1] + brj1);
            float z0 = sigf(xz.x + Dz[2*i]   + bzj0);
            float z1 = sigf(xz.y + Dz[2*i+1] + bzj1);
            float n0 = tanhf(xn.x + r0 * (Dn[2*i]   + bnj0));
            float n1 = tanhf(xn.y + r1 * (Dn[2*i+1] + bnj1));
            float h0 = (1.0f - z0) * n0 + z0 * hp0;
            float h1 = (1.0f - z1) * n1 + z1 * hp1;
            uint2 pk = splitpair(h0, h1);
            hout[(size_t)b * KP + pidx] = pk;
            if (yS) yS[((size_t)b * TT + t) * KP + pidx] = pk;
        }

        grid_sync(NBLK);
        const uint2* tmp = hin; hin = hout; hout = (uint2*)tmp;
    }
    // TT even -> final hidden ends in hS0 (the initial buffer)
}

// ---------------------------------------------------------------------------
// predictions[b] = dot(h[b,:], lin_W) + lin_b
// ---------------------------------------------------------------------------
__global__ __launch_bounds__(256) void final_pred(
    const uint2* __restrict__ hS, const float* __restrict__ W,
    const float* __restrict__ bias, float* __restrict__ out)
{
    int b = blockIdx.x;
    float s = 0.f;
    for (int p = threadIdx.x; p < KP; p += 256) {
        uint2 u = hS[(size_t)b * KP + p];
        s += (lo_f(u.x) + lo_f(u.y)) * W[2 * p]
           + (hi_f(u.x) + hi_f(u.y)) * W[2 * p + 1];
    }
    #pragma unroll
    for (int o = 16; o; o >>= 1) s += __shfl_xor_sync(0xFFFFFFFFu, s, o);
    __shared__ float ws[8];
    if ((threadIdx.x & 31) == 0) ws[threadIdx.x >> 5] = s;
    __syncthreads();
    if (threadIdx.x == 0) {
        float t = 0.f;
        #pragma unroll
        for (int k = 0; k < 8; ++k) t += ws[k];
        out[b] = t + bias[0];
    }
}

// ---------------------------------------------------------------------------
// Launch — [0] prep_misc [1] prep_weights [2] gemm [3] recur [4] gemm
// [5] recur <- ncu (-s 5 -c 1) profiles the recurrence
// ---------------------------------------------------------------------------
extern "C" void kernel_launch(void* const* d_in, const int* in_sizes, int n_in,
                              void* d_out, int out_size)
{
    const float* rand_input = (const float*)d_in[1];
    const float* h0   = (const float*)d_in[2];
    const float* Wih0 = (const float*)d_in[7];
    const float* Whh0 = (const float*)d_in[8];
    const float* bih0 = (const float*)d_in[9];
    const float* bhh0 = (const float*)d_in[10];
    const float* Wih1 = (const float*)d_in[11];
    const float* Whh1 = (const float*)d_in[12];
    const float* bih1 = (const float*)d_in[13];
    const float* bhh1 = (const float*)d_in[14];
    const float* linW = (const float*)d_in[15];
    const float* linb = (const float*)d_in[16];
    float* out = (float*)d_out;

    float *xg;
    uint2 *inS, *yAS, *yBS, *WihS, *WhhS, *hA, *hB, *hC;
    cudaGetSymbolAddress((void**)&xg,   g_xg);
    cudaGetSymbolAddress((void**)&inS,  g_inS);
    cudaGetSymbolAddress((void**)&yAS,  g_yAS);
    cudaGetSymbolAddress((void**)&yBS,  g_yBS);
    cudaGetSymbolAddress((void**)&WihS, g_WihS);
    cudaGetSymbolAddress((void**)&WhhS, g_WhhS);
    cudaGetSymbolAddress((void**)&hA,   g_hA);
    cudaGetSymbolAddress((void**)&hB,   g_hB);
    cudaGetSymbolAddress((void**)&hC,   g_hC);
    uint2* WihS1 = WihS + (size_t)N3 * KP;
    uint2* WhhS1 = WhhS + (size_t)N3 * KP;

    cudaFuncSetAttribute(gru_recurrence,
                         cudaFuncAttributeMaxDynamicSharedMemorySize, REC_SMEM);
    cudaFuncSetAttribute(gemm_xg,
                         cudaFuncAttributeMaxDynamicSharedMemorySize, XG_SMEM);

    dim3 blk(256);
    dim3 grid_xg(N3 / 64, MFULL / 128);       // 48 x 384

    // [0] prep: rand_input + both h0 layers
    prep_misc<<<(INPAIRS + 2 * HPAIRS + 255) / 256, blk>>>(
        (const float2*)rand_input, (const float2*)h0, inS, hA, hB);
    // [1] prep: all 4 weight matrices
    prep_weights<<<(4 * WPAIRS + 255) / 256, blk>>>(
        (const float2*)Wih0, (const float2*)Whh0,
        (const float2*)Wih1, (const float2*)Whh1,
        WihS, WhhS, WihS1, WhhS1);

    auto run_pass = [&](const uint2* x, const uint2* WihSp, const float* bih,
                        const uint2* WhhSp, const float* bhh,
                        uint2* h_init, uint2* y) {
        gemm_xg<<<grid_xg, blk, XG_SMEM>>>(x, WihSp, bih, xg);
        gru_recurrence<<<NBLK, blk, REC_SMEM>>>(xg, WhhSp, bhh, h_init, hC, y);
    };

    // [2,3] pass 1: layer0 on rand_input, h = h0[0] (hA)
    run_pass(inS, WihS, bih0, WhhS, bhh0, hA, yAS);
    // [4,5] pass 2: layer1 on yA, h = h0[1] (hB)   <- recurrence profiled
    run_pass(yAS, WihS1, bih1, WhhS1, bhh1, hB, yBS);

    // pass 3: layer0 on yB, h = 0
    cudaMemsetAsync(hA, 0, (size_t)HPAIRS * sizeof(uint2));
    run_pass(yBS, WihS, bih0, WhhS, bhh0, hA, yAS);

    // pass 4: layer1 on yA, h = 0 (y not needed)
    cudaMemsetAsync(hB, 0, (size_t)HPAIRS * sizeof(uint2));
    run_pass(yAS, WihS1, bih1, WhhS1, bhh1, hB, nullptr);

    final_pred<<<BB, blk>>>(hB, linW, linb, out);
}